// round 1
// baseline (speedup 1.0000x reference)
#include <cuda_runtime.h>
#include <math.h>

#define S_LEN 2048
#define EMB   1024
#define NH    16
#define HD    64
#define CLM1  1023          // cache length (CL-1)
#define INDIM (S_LEN + CLM1)  // 3071 total keys
#define WIN   1024          // attention window

// Scratch (allocation-free rule: device globals)
__device__ float g_Q[S_LEN * EMB];
__device__ float g_K[S_LEN * EMB];
__device__ float g_V[S_LEN * EMB];
__device__ float g_O[S_LEN * EMB];

// ---------------------------------------------------------------------------
// SGEMM: C[M,N] = A[M,K] * B[N,K]^T + bias[N]   (both row-major, K contiguous)
// 128x128 block tile, BK=8, 256 threads, 8x8 per thread (split 2x2 of 4x4).
// ---------------------------------------------------------------------------
__global__ __launch_bounds__(256) void sgemm_nt(
    const float* __restrict__ A, const float* __restrict__ B,
    const float* __restrict__ bias, float* __restrict__ C,
    int M, int N, int K)
{
    __shared__ float As[8][128];
    __shared__ float Bs[8][128];
    const int t  = threadIdx.x;
    const int tx = t & 15;
    const int ty = t >> 4;
    const int m0 = blockIdx.y * 128;
    const int n0 = blockIdx.x * 128;
    const int lr = t >> 1;          // 0..127
    const int lc = (t & 1) << 2;    // 0 or 4

    float acc[8][8];
#pragma unroll
    for (int i = 0; i < 8; ++i)
#pragma unroll
        for (int j = 0; j < 8; ++j) acc[i][j] = 0.f;

    const float* Aptr = A + (size_t)(m0 + lr) * K + lc;
    const float* Bptr = B + (size_t)(n0 + lr) * K + lc;

    for (int k0 = 0; k0 < K; k0 += 8) {
        float4 a4 = *reinterpret_cast<const float4*>(Aptr + k0);
        float4 b4 = *reinterpret_cast<const float4*>(Bptr + k0);
        As[lc+0][lr] = a4.x; As[lc+1][lr] = a4.y;
        As[lc+2][lr] = a4.z; As[lc+3][lr] = a4.w;
        Bs[lc+0][lr] = b4.x; Bs[lc+1][lr] = b4.y;
        Bs[lc+2][lr] = b4.z; Bs[lc+3][lr] = b4.w;
        __syncthreads();
#pragma unroll
        for (int kk = 0; kk < 8; ++kk) {
            float ra[8], rb[8];
#pragma unroll
            for (int i = 0; i < 4; ++i) {
                ra[i]   = As[kk][ty*4 + i];
                ra[4+i] = As[kk][64 + ty*4 + i];
                rb[i]   = Bs[kk][tx*4 + i];
                rb[4+i] = Bs[kk][64 + tx*4 + i];
            }
#pragma unroll
            for (int i = 0; i < 8; ++i)
#pragma unroll
                for (int j = 0; j < 8; ++j)
                    acc[i][j] = fmaf(ra[i], rb[j], acc[i][j]);
        }
        __syncthreads();
    }
#pragma unroll
    for (int i = 0; i < 8; ++i) {
        int m = m0 + ((i < 4) ? (ty*4 + i) : (64 + ty*4 + (i - 4)));
#pragma unroll
        for (int j = 0; j < 8; ++j) {
            int n = n0 + ((j < 4) ? (tx*4 + j) : (64 + tx*4 + (j - 4)));
            C[(size_t)m * N + n] = acc[i][j] + bias[n];
        }
    }
}

// ---------------------------------------------------------------------------
// RoPE applied in-place to Q and K. One thread per (token, head, dim-pair).
// Mirrors the reference fp32 math: freq = exp(-d * (ln(1e4)/32)) in f32,
// angle = (float)(s+pos) * freq with a single f32 rounding.
// ---------------------------------------------------------------------------
__global__ void rope_qk(float* __restrict__ Q, float* __restrict__ K,
                        const int* __restrict__ pos)
{
    int idx = blockIdx.x * blockDim.x + threadIdx.x;
    if (idx >= S_LEN * NH * (HD / 2)) return;
    int d = idx & 31;
    int n = (idx >> 5) & 15;
    int s = idx >> 9;
    const float c = 0.28782313662425583f;       // ln(10000)/32
    float freq = expf(-(float)d * c);
    float ang  = __fmul_rn((float)(s + pos[0]), freq);
    float sn, cs;
    sincosf(ang, &sn, &cs);
    size_t base = (size_t)s * EMB + n * HD + 2 * d;
    float qe = Q[base], qo = Q[base + 1];
    Q[base]     = qe * cs - qo * sn;
    Q[base + 1] = qe * sn + qo * cs;
    float ke = K[base], ko = K[base + 1];
    K[base]     = ke * cs - ko * sn;
    K[base + 1] = ke * sn + ko * cs;
}

// ---------------------------------------------------------------------------
// Flash attention with sliding window over the concatenated key axis.
// Block = (head n, 64-query tile). 256 threads; thread (ty,tx) owns a 4x4 tile.
// Key window for the tile: concat indices [q0, q0 + 1087) -> 17 blocks of 64.
// kk < 1023 reads cache; otherwise new K/V at s = kk - 1023.
// ---------------------------------------------------------------------------
__global__ __launch_bounds__(256) void attn_kernel(
    const float* __restrict__ Q, const float* __restrict__ K,
    const float* __restrict__ V, const float* __restrict__ kc,
    const float* __restrict__ vc, float* __restrict__ Og)
{
    extern __shared__ float sm[];
    float* Qs   = sm;              // 64 x 65
    float* Ks   = Qs + 64 * 65;    // 64 x 65
    float* Vs   = Ks + 64 * 65;    // 64 x 65
    float* Ss   = Vs + 64 * 65;    // 64 x 65
    float* mrow = Ss + 64 * 65;    // 64
    float* lrow = mrow + 64;       // 64
    float* arow = lrow + 64;       // 64

    const int n  = blockIdx.y;
    const int q0 = blockIdx.x * 64;
    const int t  = threadIdx.x;
    const int tx = t & 15, ty = t >> 4;

    // Load + pre-scale Q tile (1/sqrt(64) = 0.125)
    for (int i = t; i < 64 * 16; i += 256) {
        int qi = i >> 4, d4 = (i & 15) << 2;
        float4 v4 = *reinterpret_cast<const float4*>(
            &Q[(size_t)(q0 + qi) * EMB + n * HD + d4]);
        float* p = &Qs[qi * 65 + d4];
        p[0] = v4.x * 0.125f; p[1] = v4.y * 0.125f;
        p[2] = v4.z * 0.125f; p[3] = v4.w * 0.125f;
    }
    if (t < 64) { mrow[t] = -1e30f; lrow[t] = 0.f; }
    float acc[4][4] = {};
    __syncthreads();

    for (int kb = 0; kb < 17; ++kb) {
        const int kstart = q0 + kb * 64;
        // Load K/V key-block (gather cache vs new)
        for (int i = t; i < 64 * 16; i += 256) {
            int r = i >> 4, d4 = (i & 15) << 2;
            int kk = kstart + r;
            float4 kv = make_float4(0.f, 0.f, 0.f, 0.f);
            float4 vv = make_float4(0.f, 0.f, 0.f, 0.f);
            if (kk < CLM1) {
                kv = *reinterpret_cast<const float4*>(&kc[(size_t)kk * EMB + n * HD + d4]);
                vv = *reinterpret_cast<const float4*>(&vc[(size_t)kk * EMB + n * HD + d4]);
            } else if (kk < INDIM) {
                int s = kk - CLM1;
                kv = *reinterpret_cast<const float4*>(&K[(size_t)s * EMB + n * HD + d4]);
                vv = *reinterpret_cast<const float4*>(&V[(size_t)s * EMB + n * HD + d4]);
            }
            float* pk = &Ks[r * 65 + d4];
            pk[0] = kv.x; pk[1] = kv.y; pk[2] = kv.z; pk[3] = kv.w;
            float* pv = &Vs[r * 65 + d4];
            pv[0] = vv.x; pv[1] = vv.y; pv[2] = vv.z; pv[3] = vv.w;
        }
        __syncthreads();

        // S = Q * K^T (64x64), each thread a 4x4 micro-tile
        float sc[4][4] = {};
#pragma unroll 8
        for (int d = 0; d < 64; ++d) {
            float ra[4], rb[4];
#pragma unroll
            for (int i = 0; i < 4; ++i) {
                ra[i] = Qs[(ty * 4 + i) * 65 + d];
                rb[i] = Ks[(tx * 4 + i) * 65 + d];
            }
#pragma unroll
            for (int i = 0; i < 4; ++i)
#pragma unroll
                for (int j = 0; j < 4; ++j)
                    sc[i][j] = fmaf(ra[i], rb[j], sc[i][j]);
        }
        // Mask + stage scores
#pragma unroll
        for (int i = 0; i < 4; ++i) {
            int qg = q0 + ty * 4 + i;
#pragma unroll
            for (int j = 0; j < 4; ++j) {
                int kk = kstart + tx * 4 + j;
                bool ok = (kk >= qg) && (kk < qg + WIN) && (kk < INDIM);
                Ss[(ty * 4 + i) * 65 + tx * 4 + j] = ok ? sc[i][j] : -1e30f;
            }
        }
        __syncthreads();

        // Online softmax: 4 threads per row (consecutive lanes), 16 cols each
        {
            int row = t >> 2, seg = t & 3;
            float* srow = &Ss[row * 65 + seg * 16];
            float mloc = -1e30f;
#pragma unroll
            for (int j = 0; j < 16; ++j) mloc = fmaxf(mloc, srow[j]);
            mloc = fmaxf(mloc, __shfl_xor_sync(0xffffffffu, mloc, 1));
            mloc = fmaxf(mloc, __shfl_xor_sync(0xffffffffu, mloc, 2));
            float mold = mrow[row];
            float mnew = fmaxf(mold, mloc);
            float psum = 0.f;
#pragma unroll
            for (int j = 0; j < 16; ++j) {
                float sv = srow[j];
                float p  = (sv > -1e29f) ? __expf(sv - mnew) : 0.f;
                srow[j] = p;
                psum += p;
            }
            psum += __shfl_xor_sync(0xffffffffu, psum, 1);
            psum += __shfl_xor_sync(0xffffffffu, psum, 2);
            if (seg == 0) {
                float al = __expf(mold - mnew);
                arow[row] = al;
                lrow[row] = lrow[row] * al + psum;
                mrow[row] = mnew;
            }
        }
        __syncthreads();

        // O = O*alpha + P * V
        float alv[4];
#pragma unroll
        for (int i = 0; i < 4; ++i) alv[i] = arow[ty * 4 + i];
#pragma unroll
        for (int i = 0; i < 4; ++i)
#pragma unroll
            for (int j = 0; j < 4; ++j) acc[i][j] *= alv[i];
#pragma unroll 8
        for (int d = 0; d < 64; ++d) {
            float ra[4], rb[4];
#pragma unroll
            for (int i = 0; i < 4; ++i) {
                ra[i] = Ss[(ty * 4 + i) * 65 + d];
                rb[i] = Vs[d * 65 + tx * 4 + i];
            }
#pragma unroll
            for (int i = 0; i < 4; ++i)
#pragma unroll
                for (int j = 0; j < 4; ++j)
                    acc[i][j] = fmaf(ra[i], rb[j], acc[i][j]);
        }
        __syncthreads();
    }

    float linv[4];
#pragma unroll
    for (int i = 0; i < 4; ++i) linv[i] = 1.f / lrow[ty * 4 + i];
#pragma unroll
    for (int i = 0; i < 4; ++i)
#pragma unroll
        for (int j = 0; j < 4; ++j)
            Og[(size_t)(q0 + ty * 4 + i) * EMB + n * HD + tx * 4 + j] =
                acc[i][j] * linv[i];
}

// new_k / new_v = roped-K / V rows [1025, 2048) -> d_out tail
__global__ void copy_kv(const float* __restrict__ K, const float* __restrict__ V,
                        float* __restrict__ ok, float* __restrict__ ov)
{
    int i = blockIdx.x * blockDim.x + threadIdx.x;
    if (i < CLM1 * EMB) {
        size_t src = (size_t)(S_LEN - CLM1) * EMB + i;
        ok[i] = K[src];
        ov[i] = V[src];
    }
}

extern "C" void kernel_launch(void* const* d_in, const int* in_sizes, int n_in,
                              void* d_out, int out_size)
{
    (void)in_sizes; (void)n_in; (void)out_size;
    const float* x  = (const float*)d_in[0];
    const float* Wq = (const float*)d_in[1];
    const float* bq = (const float*)d_in[2];
    const float* Wk = (const float*)d_in[3];
    const float* bk = (const float*)d_in[4];
    const float* Wv = (const float*)d_in[5];
    const float* bv = (const float*)d_in[6];
    const float* Wo = (const float*)d_in[7];
    const float* bo = (const float*)d_in[8];
    const float* kc = (const float*)d_in[9];
    const float* vc = (const float*)d_in[10];
    const int*  pos = (const int*)d_in[11];
    float* out = (float*)d_out;

    float *Q, *K, *V, *O;
    cudaGetSymbolAddress((void**)&Q, g_Q);
    cudaGetSymbolAddress((void**)&K, g_K);
    cudaGetSymbolAddress((void**)&V, g_V);
    cudaGetSymbolAddress((void**)&O, g_O);

    dim3 gg(EMB / 128, S_LEN / 128);   // (8, 16)
    sgemm_nt<<<gg, 256>>>(x, Wq, bq, Q, S_LEN, EMB, EMB);
    sgemm_nt<<<gg, 256>>>(x, Wk, bk, K, S_LEN, EMB, EMB);
    sgemm_nt<<<gg, 256>>>(x, Wv, bv, V, S_LEN, EMB, EMB);

    rope_qk<<<(S_LEN * NH * (HD / 2) + 255) / 256, 256>>>(Q, K, pos);

    size_t smem = (4 * 64 * 65 + 3 * 64) * sizeof(float);  // ~67 KB
    cudaFuncSetAttribute(attn_kernel,
                         cudaFuncAttributeMaxDynamicSharedMemorySize, (int)smem);
    attn_kernel<<<dim3(S_LEN / 64, NH), 256, smem>>>(Q, K, V, kc, vc, O);

    sgemm_nt<<<gg, 256>>>(O, Wo, bo, out, S_LEN, EMB, EMB);

    copy_kv<<<(CLM1 * EMB + 255) / 256, 256>>>(
        K, V, out + (size_t)S_LEN * EMB,
        out + (size_t)S_LEN * EMB + (size_t)CLM1 * EMB);
}

// round 3
// speedup vs baseline: 1.7975x; 1.7975x over previous
#include <cuda_runtime.h>
#include <cuda_bf16.h>
#include <math.h>
#include <stdint.h>

#define S_LEN 2048
#define EMB   1024
#define NH    16
#define HD    64
#define CLM1  1023
#define INDIM (S_LEN + CLM1)
#define WIN   1024

// Scratch (allocation-free rule: device globals)
__device__ float g_Q[S_LEN * EMB];
__device__ float g_K[S_LEN * EMB];
__device__ float g_V[S_LEN * EMB];
__device__ float g_O[S_LEN * EMB];

// ---------------------------------------------------------------------------
// bf16-split GEMM via mma.sync (HMMA): C[M,1024] = A @ W^T + bias.
// A, W row-major K-contiguous. 128x128 CTA tile, BK=32 fp32 per chunk.
// Split fp32 -> bf16 hi+lo; 3 passes (hi*hi, hi*lo, lo*hi), lo*lo dropped.
// 8 warps = 4(m) x 2(n); warp tile 32x64 = 2x8 m16n8k16 micro-tiles.
// gridDim.z picks weight/bias/output set (fused QKV).
// ---------------------------------------------------------------------------
#define GPITCH 40   // bf16 elements per smem row (conflict-free)

__device__ __forceinline__ void mma16816(
    float c[4], const uint32_t a[4], uint32_t b0, uint32_t b1)
{
    asm volatile(
        "mma.sync.aligned.m16n8k16.row.col.f32.bf16.bf16.f32 "
        "{%0,%1,%2,%3}, {%4,%5,%6,%7}, {%8,%9}, {%0,%1,%2,%3};"
        : "+f"(c[0]), "+f"(c[1]), "+f"(c[2]), "+f"(c[3])
        : "r"(a[0]), "r"(a[1]), "r"(a[2]), "r"(a[3]), "r"(b0), "r"(b1));
}

__device__ __forceinline__ uint32_t pack_hi(float x, float y,
                                            float& lx, float& ly)
{
    __nv_bfloat16 hx = __float2bfloat16(x);
    __nv_bfloat16 hy = __float2bfloat16(y);
    lx = x - __bfloat162float(hx);
    ly = y - __bfloat162float(hy);
    __nv_bfloat162 h2(hx, hy);
    return *reinterpret_cast<uint32_t*>(&h2);
}
__device__ __forceinline__ uint32_t pack_lo(float lx, float ly)
{
    __nv_bfloat162 l2(__float2bfloat16(lx), __float2bfloat16(ly));
    return *reinterpret_cast<uint32_t*>(&l2);
}

__global__ __launch_bounds__(256) void gemm_mma(
    const float* __restrict__ A,
    const float* __restrict__ W0, const float* __restrict__ W1, const float* __restrict__ W2,
    const float* __restrict__ b0p, const float* __restrict__ b1p, const float* __restrict__ b2p,
    float* __restrict__ C0, float* __restrict__ C1, float* __restrict__ C2)
{
    const float* W    = (blockIdx.z == 0) ? W0 : (blockIdx.z == 1) ? W1 : W2;
    const float* bias = (blockIdx.z == 0) ? b0p : (blockIdx.z == 1) ? b1p : b2p;
    float*       C    = (blockIdx.z == 0) ? C0 : (blockIdx.z == 1) ? C1 : C2;

    __shared__ __nv_bfloat16 Ah[128 * GPITCH];
    __shared__ __nv_bfloat16 Al[128 * GPITCH];
    __shared__ __nv_bfloat16 Bh[128 * GPITCH];
    __shared__ __nv_bfloat16 Bl[128 * GPITCH];
    __shared__ float biass[128];

    const int t      = threadIdx.x;
    const int lane   = t & 31;
    const int wid    = t >> 5;
    const int warp_m = wid >> 1;      // 0..3
    const int warp_n = wid & 1;      // 0..1
    const int g      = lane >> 2;    // 0..7
    const int t4     = lane & 3;     // 0..3
    const int m0     = blockIdx.y * 128;
    const int n0     = blockIdx.x * 128;

    if (t < 128) biass[t] = bias[n0 + t];

    // load slots: idx = i*256 + t ; row = idx>>3 (0..127), col = (idx&7)*4
    const int lrow = t >> 3 ;        // base row for i=0 (rows advance by 32 per i)
    const int lcol = (t & 7) * 4;

    float4 ra[4], rb[4];
#pragma unroll
    for (int i = 0; i < 4; ++i) {
        int row = lrow + i * 32;
        ra[i] = *(const float4*)(A + (size_t)(m0 + row) * EMB + lcol);
        rb[i] = *(const float4*)(W + (size_t)(n0 + row) * EMB + lcol);
    }

    float acc[2][8][4];
#pragma unroll
    for (int mi = 0; mi < 2; ++mi)
#pragma unroll
        for (int ni = 0; ni < 8; ++ni)
#pragma unroll
            for (int j = 0; j < 4; ++j) acc[mi][ni][j] = 0.f;

    for (int c = 0; c < 32; ++c) {
        // convert + store chunk c
#pragma unroll
        for (int i = 0; i < 4; ++i) {
            int row = lrow + i * 32;
            int off = row * GPITCH + lcol;
            float lx, ly, lz, lw;
            uint32_t h01 = pack_hi(ra[i].x, ra[i].y, lx, ly);
            uint32_t h23 = pack_hi(ra[i].z, ra[i].w, lz, lw);
            *(uint32_t*)&Ah[off]     = h01;
            *(uint32_t*)&Ah[off + 2] = h23;
            *(uint32_t*)&Al[off]     = pack_lo(lx, ly);
            *(uint32_t*)&Al[off + 2] = pack_lo(lz, lw);
            h01 = pack_hi(rb[i].x, rb[i].y, lx, ly);
            h23 = pack_hi(rb[i].z, rb[i].w, lz, lw);
            *(uint32_t*)&Bh[off]     = h01;
            *(uint32_t*)&Bh[off + 2] = h23;
            *(uint32_t*)&Bl[off]     = pack_lo(lx, ly);
            *(uint32_t*)&Bl[off + 2] = pack_lo(lz, lw);
        }
        __syncthreads();

        // prefetch chunk c+1
        if (c < 31) {
            int k0 = (c + 1) * 32;
#pragma unroll
            for (int i = 0; i < 4; ++i) {
                int row = lrow + i * 32;
                ra[i] = *(const float4*)(A + (size_t)(m0 + row) * EMB + k0 + lcol);
                rb[i] = *(const float4*)(W + (size_t)(n0 + row) * EMB + k0 + lcol);
            }
        }

        // 3 passes: (Ah,Bh), (Ah,Bl), (Al,Bh)
#pragma unroll
        for (int pass = 0; pass < 3; ++pass) {
            const __nv_bfloat16* Ab = (pass == 2) ? Al : Ah;
            const __nv_bfloat16* Bb = (pass == 1) ? Bl : Bh;
#pragma unroll
            for (int ks = 0; ks < 2; ++ks) {
                const int kb = ks * 16 + t4 * 2;
                uint32_t afr[2][4];
#pragma unroll
                for (int mi = 0; mi < 2; ++mi) {
                    int r = warp_m * 32 + mi * 16 + g;
                    afr[mi][0] = *(const uint32_t*)&Ab[r * GPITCH + kb];
                    afr[mi][1] = *(const uint32_t*)&Ab[(r + 8) * GPITCH + kb];
                    afr[mi][2] = *(const uint32_t*)&Ab[r * GPITCH + kb + 8];
                    afr[mi][3] = *(const uint32_t*)&Ab[(r + 8) * GPITCH + kb + 8];
                }
#pragma unroll
                for (int ni = 0; ni < 8; ++ni) {
                    int n = warp_n * 64 + ni * 8 + g;
                    uint32_t bb0 = *(const uint32_t*)&Bb[n * GPITCH + kb];
                    uint32_t bb1 = *(const uint32_t*)&Bb[n * GPITCH + kb + 8];
                    mma16816(acc[0][ni], afr[0], bb0, bb1);
                    mma16816(acc[1][ni], afr[1], bb0, bb1);
                }
            }
        }
        __syncthreads();
    }

    // epilogue: add bias, write
#pragma unroll
    for (int mi = 0; mi < 2; ++mi) {
        int r0 = m0 + warp_m * 32 + mi * 16 + g;
#pragma unroll
        for (int ni = 0; ni < 8; ++ni) {
            int cc = warp_n * 64 + ni * 8 + t4 * 2;
            float bx = biass[cc], by = biass[cc + 1];
            float2 v0 = make_float2(acc[mi][ni][0] + bx, acc[mi][ni][1] + by);
            float2 v1 = make_float2(acc[mi][ni][2] + bx, acc[mi][ni][3] + by);
            *(float2*)(C + (size_t)r0 * EMB + n0 + cc)       = v0;
            *(float2*)(C + (size_t)(r0 + 8) * EMB + n0 + cc) = v1;
        }
    }
}

// ---------------------------------------------------------------------------
// RoPE applied in-place to Q and K (fp32, mirrors reference math)
// ---------------------------------------------------------------------------
__global__ void rope_qk(float* __restrict__ Q, float* __restrict__ K,
                        const int* __restrict__ pos)
{
    int idx = blockIdx.x * blockDim.x + threadIdx.x;
    if (idx >= S_LEN * NH * (HD / 2)) return;
    int d = idx & 31;
    int n = (idx >> 5) & 15;
    int s = idx >> 9;
    const float c = 0.28782313662425583f;       // ln(10000)/32
    float freq = expf(-(float)d * c);
    float ang  = __fmul_rn((float)(s + pos[0]), freq);
    float sn, cs;
    sincosf(ang, &sn, &cs);
    size_t base = (size_t)s * EMB + n * HD + 2 * d;
    float qe = Q[base], qo = Q[base + 1];
    Q[base]     = qe * cs - qo * sn;
    Q[base + 1] = qe * sn + qo * cs;
    float ke = K[base], ko = K[base + 1];
    K[base]     = ke * cs - ko * sn;
    K[base + 1] = ke * sn + ko * cs;
}

// ---------------------------------------------------------------------------
// Flash attention (fp32 CUDA cores) — unchanged from R1 (passing baseline)
// ---------------------------------------------------------------------------
__global__ __launch_bounds__(256) void attn_kernel(
    const float* __restrict__ Q, const float* __restrict__ K,
    const float* __restrict__ V, const float* __restrict__ kc,
    const float* __restrict__ vc, float* __restrict__ Og)
{
    extern __shared__ float sm[];
    float* Qs   = sm;
    float* Ks   = Qs + 64 * 65;
    float* Vs   = Ks + 64 * 65;
    float* Ss   = Vs + 64 * 65;
    float* mrow = Ss + 64 * 65;
    float* lrow = mrow + 64;
    float* arow = lrow + 64;

    const int n  = blockIdx.y;
    const int q0 = blockIdx.x * 64;
    const int t  = threadIdx.x;
    const int tx = t & 15, ty = t >> 4;

    for (int i = t; i < 64 * 16; i += 256) {
        int qi = i >> 4, d4 = (i & 15) << 2;
        float4 v4 = *reinterpret_cast<const float4*>(
            &Q[(size_t)(q0 + qi) * EMB + n * HD + d4]);
        float* p = &Qs[qi * 65 + d4];
        p[0] = v4.x * 0.125f; p[1] = v4.y * 0.125f;
        p[2] = v4.z * 0.125f; p[3] = v4.w * 0.125f;
    }
    if (t < 64) { mrow[t] = -1e30f; lrow[t] = 0.f; }
    float acc[4][4] = {};
    __syncthreads();

    for (int kb = 0; kb < 17; ++kb) {
        const int kstart = q0 + kb * 64;
        for (int i = t; i < 64 * 16; i += 256) {
            int r = i >> 4, d4 = (i & 15) << 2;
            int kk = kstart + r;
            float4 kv = make_float4(0.f, 0.f, 0.f, 0.f);
            float4 vv = make_float4(0.f, 0.f, 0.f, 0.f);
            if (kk < CLM1) {
                kv = *reinterpret_cast<const float4*>(&kc[(size_t)kk * EMB + n * HD + d4]);
                vv = *reinterpret_cast<const float4*>(&vc[(size_t)kk * EMB + n * HD + d4]);
            } else if (kk < INDIM) {
                int s = kk - CLM1;
                kv = *reinterpret_cast<const float4*>(&K[(size_t)s * EMB + n * HD + d4]);
                vv = *reinterpret_cast<const float4*>(&V[(size_t)s * EMB + n * HD + d4]);
            }
            float* pk = &Ks[r * 65 + d4];
            pk[0] = kv.x; pk[1] = kv.y; pk[2] = kv.z; pk[3] = kv.w;
            float* pv = &Vs[r * 65 + d4];
            pv[0] = vv.x; pv[1] = vv.y; pv[2] = vv.z; pv[3] = vv.w;
        }
        __syncthreads();

        float sc[4][4] = {};
#pragma unroll 8
        for (int d = 0; d < 64; ++d) {
            float rra[4], rrb[4];
#pragma unroll
            for (int i = 0; i < 4; ++i) {
                rra[i] = Qs[(ty * 4 + i) * 65 + d];
                rrb[i] = Ks[(tx * 4 + i) * 65 + d];
            }
#pragma unroll
            for (int i = 0; i < 4; ++i)
#pragma unroll
                for (int j = 0; j < 4; ++j)
                    sc[i][j] = fmaf(rra[i], rrb[j], sc[i][j]);
        }
#pragma unroll
        for (int i = 0; i < 4; ++i) {
            int qg = q0 + ty * 4 + i;
#pragma unroll
            for (int j = 0; j < 4; ++j) {
                int kk = kstart + tx * 4 + j;
                bool ok = (kk >= qg) && (kk < qg + WIN) && (kk < INDIM);
                Ss[(ty * 4 + i) * 65 + tx * 4 + j] = ok ? sc[i][j] : -1e30f;
            }
        }
        __syncthreads();

        {
            int row = t >> 2, seg = t & 3;
            float* srow = &Ss[row * 65 + seg * 16];
            float mloc = -1e30f;
#pragma unroll
            for (int j = 0; j < 16; ++j) mloc = fmaxf(mloc, srow[j]);
            mloc = fmaxf(mloc, __shfl_xor_sync(0xffffffffu, mloc, 1));
            mloc = fmaxf(mloc, __shfl_xor_sync(0xffffffffu, mloc, 2));
            float mold = mrow[row];
            float mnew = fmaxf(mold, mloc);
            float psum = 0.f;
#pragma unroll
            for (int j = 0; j < 16; ++j) {
                float sv = srow[j];
                float p  = (sv > -1e29f) ? __expf(sv - mnew) : 0.f;
                srow[j] = p;
                psum += p;
            }
            psum += __shfl_xor_sync(0xffffffffu, psum, 1);
            psum += __shfl_xor_sync(0xffffffffu, psum, 2);
            if (seg == 0) {
                float al = __expf(mold - mnew);
                arow[row] = al;
                lrow[row] = lrow[row] * al + psum;
                mrow[row] = mnew;
            }
        }
        __syncthreads();

        float alv[4];
#pragma unroll
        for (int i = 0; i < 4; ++i) alv[i] = arow[ty * 4 + i];
#pragma unroll
        for (int i = 0; i < 4; ++i)
#pragma unroll
            for (int j = 0; j < 4; ++j) acc[i][j] *= alv[i];
#pragma unroll 8
        for (int d = 0; d < 64; ++d) {
            float rra[4], rrb[4];
#pragma unroll
            for (int i = 0; i < 4; ++i) {
                rra[i] = Ss[(ty * 4 + i) * 65 + d];
                rrb[i] = Vs[d * 65 + tx * 4 + i];
            }
#pragma unroll
            for (int i = 0; i < 4; ++i)
#pragma unroll
                for (int j = 0; j < 4; ++j)
                    acc[i][j] = fmaf(rra[i], rrb[j], acc[i][j]);
        }
        __syncthreads();
    }

    float linv[4];
#pragma unroll
    for (int i = 0; i < 4; ++i) linv[i] = 1.f / lrow[ty * 4 + i];
#pragma unroll
    for (int i = 0; i < 4; ++i)
#pragma unroll
        for (int j = 0; j < 4; ++j)
            Og[(size_t)(q0 + ty * 4 + i) * EMB + n * HD + tx * 4 + j] =
                acc[i][j] * linv[i];
}

__global__ void copy_kv(const float* __restrict__ K, const float* __restrict__ V,
                        float* __restrict__ ok, float* __restrict__ ov)
{
    int i = blockIdx.x * blockDim.x + threadIdx.x;
    if (i < CLM1 * EMB) {
        size_t src = (size_t)(S_LEN - CLM1) * EMB + i;
        ok[i] = K[src];
        ov[i] = V[src];
    }
}

extern "C" void kernel_launch(void* const* d_in, const int* in_sizes, int n_in,
                              void* d_out, int out_size)
{
    (void)in_sizes; (void)n_in; (void)out_size;
    const float* x  = (const float*)d_in[0];
    const float* Wq = (const float*)d_in[1];
    const float* bq = (const float*)d_in[2];
    const float* Wk = (const float*)d_in[3];
    const float* bk = (const float*)d_in[4];
    const float* Wv = (const float*)d_in[5];
    const float* bv = (const float*)d_in[6];
    const float* Wo = (const float*)d_in[7];
    const float* bo = (const float*)d_in[8];
    const float* kc = (const float*)d_in[9];
    const float* vc = (const float*)d_in[10];
    const int*  pos = (const int*)d_in[11];
    float* out = (float*)d_out;

    float *Q, *K, *V, *O;
    cudaGetSymbolAddress((void**)&Q, g_Q);
    cudaGetSymbolAddress((void**)&K, g_K);
    cudaGetSymbolAddress((void**)&V, g_V);
    cudaGetSymbolAddress((void**)&O, g_O);

    // QKV fused (z = 0,1,2)
    gemm_mma<<<dim3(EMB / 128, S_LEN / 128, 3), 256>>>(
        x, Wq, Wk, Wv, bq, bk, bv, Q, K, V);

    rope_qk<<<(S_LEN * NH * (HD / 2) + 255) / 256, 256>>>(Q, K, pos);

    size_t smem = (4 * 64 * 65 + 3 * 64) * sizeof(float);
    cudaFuncSetAttribute(attn_kernel,
                         cudaFuncAttributeMaxDynamicSharedMemorySize, (int)smem);
    attn_kernel<<<dim3(S_LEN / 64, NH), 256, smem>>>(Q, K, V, kc, vc, O);

    // Output projection
    gemm_mma<<<dim3(EMB / 128, S_LEN / 128, 1), 256>>>(
        O, Wo, Wo, Wo, bo, bo, bo, out, out, out);

    copy_kv<<<(CLM1 * EMB + 255) / 256, 256>>>(
        K, V, out + (size_t)S_LEN * EMB,
        out + (size_t)S_LEN * EMB + (size_t)CLM1 * EMB);
}

// round 4
// speedup vs baseline: 2.4967x; 1.3890x over previous
#include <cuda_runtime.h>
#include <cuda_bf16.h>
#include <math.h>
#include <stdint.h>

#define S_LEN 2048
#define EMB   1024
#define NH    16
#define HD    64
#define CLM1  1023
#define INDIM (S_LEN + CLM1)   // 3071
#define KVROWS 3072            // padded
#define WIN   1024

// Scratch (allocation-free rule: device globals)
__device__ float g_Q[S_LEN * EMB];
__device__ float g_K[S_LEN * EMB];
__device__ float g_V[S_LEN * EMB];
__device__ float g_O[S_LEN * EMB];
__device__ __nv_bfloat16 g_Qh[S_LEN * EMB];
__device__ __nv_bfloat16 g_Ql[S_LEN * EMB];
__device__ __nv_bfloat16 g_KH[KVROWS * EMB];
__device__ __nv_bfloat16 g_KL[KVROWS * EMB];
__device__ __nv_bfloat16 g_VH[KVROWS * EMB];
__device__ __nv_bfloat16 g_VL[KVROWS * EMB];

// ---------------------------------------------------------------------------
// helpers
// ---------------------------------------------------------------------------
__device__ __forceinline__ void mma16816(
    float c[4], const uint32_t a[4], uint32_t b0, uint32_t b1)
{
    asm volatile(
        "mma.sync.aligned.m16n8k16.row.col.f32.bf16.bf16.f32 "
        "{%0,%1,%2,%3}, {%4,%5,%6,%7}, {%8,%9}, {%0,%1,%2,%3};"
        : "+f"(c[0]), "+f"(c[1]), "+f"(c[2]), "+f"(c[3])
        : "r"(a[0]), "r"(a[1]), "r"(a[2]), "r"(a[3]), "r"(b0), "r"(b1));
}
__device__ __forceinline__ uint32_t pack_hi(float x, float y,
                                            float& lx, float& ly)
{
    __nv_bfloat16 hx = __float2bfloat16(x);
    __nv_bfloat16 hy = __float2bfloat16(y);
    lx = x - __bfloat162float(hx);
    ly = y - __bfloat162float(hy);
    __nv_bfloat162 h2(hx, hy);
    return *reinterpret_cast<uint32_t*>(&h2);
}
__device__ __forceinline__ uint32_t pack_lo(float lx, float ly)
{
    __nv_bfloat162 l2(__float2bfloat16(lx), __float2bfloat16(ly));
    return *reinterpret_cast<uint32_t*>(&l2);
}

// ---------------------------------------------------------------------------
// bf16-split GEMM via mma.sync (unchanged from R3, passing)
// ---------------------------------------------------------------------------
#define GPITCH 40

__global__ __launch_bounds__(256) void gemm_mma(
    const float* __restrict__ A,
    const float* __restrict__ W0, const float* __restrict__ W1, const float* __restrict__ W2,
    const float* __restrict__ b0p, const float* __restrict__ b1p, const float* __restrict__ b2p,
    float* __restrict__ C0, float* __restrict__ C1, float* __restrict__ C2)
{
    const float* W    = (blockIdx.z == 0) ? W0 : (blockIdx.z == 1) ? W1 : W2;
    const float* bias = (blockIdx.z == 0) ? b0p : (blockIdx.z == 1) ? b1p : b2p;
    float*       C    = (blockIdx.z == 0) ? C0 : (blockIdx.z == 1) ? C1 : C2;

    __shared__ __nv_bfloat16 Ah[128 * GPITCH];
    __shared__ __nv_bfloat16 Al[128 * GPITCH];
    __shared__ __nv_bfloat16 Bh[128 * GPITCH];
    __shared__ __nv_bfloat16 Bl[128 * GPITCH];
    __shared__ float biass[128];

    const int t      = threadIdx.x;
    const int lane   = t & 31;
    const int wid    = t >> 5;
    const int warp_m = wid >> 1;
    const int warp_n = wid & 1;
    const int g      = lane >> 2;
    const int t4     = lane & 3;
    const int m0     = blockIdx.y * 128;
    const int n0     = blockIdx.x * 128;

    if (t < 128) biass[t] = bias[n0 + t];

    const int lrow = t >> 3;
    const int lcol = (t & 7) * 4;

    float4 ra[4], rb[4];
#pragma unroll
    for (int i = 0; i < 4; ++i) {
        int row = lrow + i * 32;
        ra[i] = *(const float4*)(A + (size_t)(m0 + row) * EMB + lcol);
        rb[i] = *(const float4*)(W + (size_t)(n0 + row) * EMB + lcol);
    }

    float acc[2][8][4];
#pragma unroll
    for (int mi = 0; mi < 2; ++mi)
#pragma unroll
        for (int ni = 0; ni < 8; ++ni)
#pragma unroll
            for (int j = 0; j < 4; ++j) acc[mi][ni][j] = 0.f;

    for (int c = 0; c < 32; ++c) {
#pragma unroll
        for (int i = 0; i < 4; ++i) {
            int row = lrow + i * 32;
            int off = row * GPITCH + lcol;
            float lx, ly, lz, lw;
            uint32_t h01 = pack_hi(ra[i].x, ra[i].y, lx, ly);
            uint32_t h23 = pack_hi(ra[i].z, ra[i].w, lz, lw);
            *(uint32_t*)&Ah[off]     = h01;
            *(uint32_t*)&Ah[off + 2] = h23;
            *(uint32_t*)&Al[off]     = pack_lo(lx, ly);
            *(uint32_t*)&Al[off + 2] = pack_lo(lz, lw);
            h01 = pack_hi(rb[i].x, rb[i].y, lx, ly);
            h23 = pack_hi(rb[i].z, rb[i].w, lz, lw);
            *(uint32_t*)&Bh[off]     = h01;
            *(uint32_t*)&Bh[off + 2] = h23;
            *(uint32_t*)&Bl[off]     = pack_lo(lx, ly);
            *(uint32_t*)&Bl[off + 2] = pack_lo(lz, lw);
        }
        __syncthreads();

        if (c < 31) {
            int k0 = (c + 1) * 32;
#pragma unroll
            for (int i = 0; i < 4; ++i) {
                int row = lrow + i * 32;
                ra[i] = *(const float4*)(A + (size_t)(m0 + row) * EMB + k0 + lcol);
                rb[i] = *(const float4*)(W + (size_t)(n0 + row) * EMB + k0 + lcol);
            }
        }

#pragma unroll
        for (int pass = 0; pass < 3; ++pass) {
            const __nv_bfloat16* Ab = (pass == 2) ? Al : Ah;
            const __nv_bfloat16* Bb = (pass == 1) ? Bl : Bh;
#pragma unroll
            for (int ks = 0; ks < 2; ++ks) {
                const int kb = ks * 16 + t4 * 2;
                uint32_t afr[2][4];
#pragma unroll
                for (int mi = 0; mi < 2; ++mi) {
                    int r = warp_m * 32 + mi * 16 + g;
                    afr[mi][0] = *(const uint32_t*)&Ab[r * GPITCH + kb];
                    afr[mi][1] = *(const uint32_t*)&Ab[(r + 8) * GPITCH + kb];
                    afr[mi][2] = *(const uint32_t*)&Ab[r * GPITCH + kb + 8];
                    afr[mi][3] = *(const uint32_t*)&Ab[(r + 8) * GPITCH + kb + 8];
                }
#pragma unroll
                for (int ni = 0; ni < 8; ++ni) {
                    int n = warp_n * 64 + ni * 8 + g;
                    uint32_t bb0 = *(const uint32_t*)&Bb[n * GPITCH + kb];
                    uint32_t bb1 = *(const uint32_t*)&Bb[n * GPITCH + kb + 8];
                    mma16816(acc[0][ni], afr[0], bb0, bb1);
                    mma16816(acc[1][ni], afr[1], bb0, bb1);
                }
            }
        }
        __syncthreads();
    }

#pragma unroll
    for (int mi = 0; mi < 2; ++mi) {
        int r0 = m0 + warp_m * 32 + mi * 16 + g;
#pragma unroll
        for (int ni = 0; ni < 8; ++ni) {
            int cc = warp_n * 64 + ni * 8 + t4 * 2;
            float bx = biass[cc], by = biass[cc + 1];
            float2 v0 = make_float2(acc[mi][ni][0] + bx, acc[mi][ni][1] + by);
            float2 v1 = make_float2(acc[mi][ni][2] + bx, acc[mi][ni][3] + by);
            *(float2*)(C + (size_t)r0 * EMB + n0 + cc)       = v0;
            *(float2*)(C + (size_t)(r0 + 8) * EMB + n0 + cc) = v1;
        }
    }
}

// ---------------------------------------------------------------------------
// RoPE in-place on Q and K (fp32)
// ---------------------------------------------------------------------------
__global__ void rope_qk(float* __restrict__ Q, float* __restrict__ K,
                        const int* __restrict__ pos)
{
    int idx = blockIdx.x * blockDim.x + threadIdx.x;
    if (idx >= S_LEN * NH * (HD / 2)) return;
    int d = idx & 31;
    int n = (idx >> 5) & 15;
    int s = idx >> 9;
    const float c = 0.28782313662425583f;
    float freq = expf(-(float)d * c);
    float ang  = __fmul_rn((float)(s + pos[0]), freq);
    float sn, cs;
    sincosf(ang, &sn, &cs);
    size_t base = (size_t)s * EMB + n * HD + 2 * d;
    float qe = Q[base], qo = Q[base + 1];
    Q[base]     = qe * cs - qo * sn;
    Q[base + 1] = qe * sn + qo * cs;
    float ke = K[base], ko = K[base + 1];
    K[base]     = ke * cs - ko * sn;
    K[base + 1] = ke * sn + ko * cs;
}

// ---------------------------------------------------------------------------
// prep: split Q (scaled) and concatenated K/V into bf16 hi/lo
// ---------------------------------------------------------------------------
__global__ void prep_q(const float* __restrict__ Q,
                       __nv_bfloat16* __restrict__ Qh, __nv_bfloat16* __restrict__ Ql)
{
    int i = blockIdx.x * blockDim.x + threadIdx.x;   // float4 index
    if (i >= S_LEN * EMB / 4) return;
    float4 v = *(const float4*)(Q + (size_t)i * 4);
    v.x *= 0.125f; v.y *= 0.125f; v.z *= 0.125f; v.w *= 0.125f;
    float lx, ly, lz, lw;
    uint32_t h01 = pack_hi(v.x, v.y, lx, ly);
    uint32_t h23 = pack_hi(v.z, v.w, lz, lw);
    *(uint2*)(Qh + (size_t)i * 4) = make_uint2(h01, h23);
    *(uint2*)(Ql + (size_t)i * 4) = make_uint2(pack_lo(lx, ly), pack_lo(lz, lw));
}

__global__ void prep_kv(const float* __restrict__ K, const float* __restrict__ V,
                        const float* __restrict__ kc, const float* __restrict__ vc,
                        __nv_bfloat16* __restrict__ KH, __nv_bfloat16* __restrict__ KL,
                        __nv_bfloat16* __restrict__ VH, __nv_bfloat16* __restrict__ VL)
{
    int i = blockIdx.x * blockDim.x + threadIdx.x;   // float4 index
    if (i >= KVROWS * EMB / 4) return;
    int kk = (i * 4) / EMB;
    int c  = (i * 4) % EMB;
    float4 kv = make_float4(0.f, 0.f, 0.f, 0.f);
    float4 vv = make_float4(0.f, 0.f, 0.f, 0.f);
    if (kk < CLM1) {
        kv = *(const float4*)(kc + (size_t)kk * EMB + c);
        vv = *(const float4*)(vc + (size_t)kk * EMB + c);
    } else if (kk < INDIM) {
        kv = *(const float4*)(K + (size_t)(kk - CLM1) * EMB + c);
        vv = *(const float4*)(V + (size_t)(kk - CLM1) * EMB + c);
    }
    float lx, ly, lz, lw;
    uint32_t h01 = pack_hi(kv.x, kv.y, lx, ly);
    uint32_t h23 = pack_hi(kv.z, kv.w, lz, lw);
    *(uint2*)(KH + (size_t)i * 4) = make_uint2(h01, h23);
    *(uint2*)(KL + (size_t)i * 4) = make_uint2(pack_lo(lx, ly), pack_lo(lz, lw));
    h01 = pack_hi(vv.x, vv.y, lx, ly);
    h23 = pack_hi(vv.z, vv.w, lz, lw);
    *(uint2*)(VH + (size_t)i * 4) = make_uint2(h01, h23);
    *(uint2*)(VL + (size_t)i * 4) = make_uint2(pack_lo(lx, ly), pack_lo(lz, lw));
}

// ---------------------------------------------------------------------------
// HMMA flash attention. Block = (64 queries, head). 4 warps, 16 rows each.
// ---------------------------------------------------------------------------
#define KPITCH 72

__global__ __launch_bounds__(128) void attn_mma(
    const __nv_bfloat16* __restrict__ Qh, const __nv_bfloat16* __restrict__ Ql,
    const __nv_bfloat16* __restrict__ KH, const __nv_bfloat16* __restrict__ KL,
    const __nv_bfloat16* __restrict__ VH, const __nv_bfloat16* __restrict__ VL,
    float* __restrict__ Og)
{
    __shared__ __nv_bfloat16 sKh[64 * KPITCH];
    __shared__ __nv_bfloat16 sKl[64 * KPITCH];
    __shared__ __nv_bfloat16 sVh[64 * KPITCH];   // transposed [d][k]
    __shared__ __nv_bfloat16 sVl[64 * KPITCH];

    const int t    = threadIdx.x;
    const int lane = t & 31;
    const int w    = t >> 5;
    const int g    = lane >> 2;
    const int t4   = lane & 3;
    const int n    = blockIdx.y;
    const int q0   = blockIdx.x * 64;
    const int r0   = q0 + w * 16 + g;       // first row of this thread

    // Q fragments (persistent)
    uint32_t qh[4][4], ql[4][4];
#pragma unroll
    for (int kt = 0; kt < 4; ++kt) {
        size_t c = (size_t)n * HD + kt * 16 + 2 * t4;
        const __nv_bfloat16* p0 = Qh + (size_t)r0 * EMB + c;
        const __nv_bfloat16* p1 = Qh + (size_t)(r0 + 8) * EMB + c;
        qh[kt][0] = *(const uint32_t*)p0;
        qh[kt][1] = *(const uint32_t*)p1;
        qh[kt][2] = *(const uint32_t*)(p0 + 8);
        qh[kt][3] = *(const uint32_t*)(p1 + 8);
        p0 = Ql + (size_t)r0 * EMB + c;
        p1 = Ql + (size_t)(r0 + 8) * EMB + c;
        ql[kt][0] = *(const uint32_t*)p0;
        ql[kt][1] = *(const uint32_t*)p1;
        ql[kt][2] = *(const uint32_t*)(p0 + 8);
        ql[kt][3] = *(const uint32_t*)(p1 + 8);
    }

    float accO[8][4];
#pragma unroll
    for (int nt = 0; nt < 8; ++nt)
#pragma unroll
        for (int j = 0; j < 4; ++j) accO[nt][j] = 0.f;
    float mr0 = -1e30f, mr1 = -1e30f, lr0 = 0.f, lr1 = 0.f;

    for (int kb = 0; kb < 17; ++kb) {
        const int kstart = q0 + kb * 64;
        // load tiles: 64 rows x 8 groups of 8 bf16
        for (int i = t; i < 512; i += 128) {
            int r = i >> 3, cg = (i & 7) * 8;
            size_t goff = (size_t)(kstart + r) * EMB + n * HD + cg;
            *(uint4*)&sKh[r * KPITCH + cg] = *(const uint4*)(KH + goff);
            *(uint4*)&sKl[r * KPITCH + cg] = *(const uint4*)(KL + goff);
            uint4 vh4 = *(const uint4*)(VH + goff);
            uint4 vl4 = *(const uint4*)(VL + goff);
            __nv_bfloat16 tmp[8];
            *(uint4*)tmp = vh4;
#pragma unroll
            for (int j = 0; j < 8; ++j) sVh[(cg + j) * KPITCH + r] = tmp[j];
            *(uint4*)tmp = vl4;
#pragma unroll
            for (int j = 0; j < 8; ++j) sVl[(cg + j) * KPITCH + r] = tmp[j];
        }
        __syncthreads();

        // S = Q K^T
        float s[8][4];
#pragma unroll
        for (int nt = 0; nt < 8; ++nt)
#pragma unroll
            for (int j = 0; j < 4; ++j) s[nt][j] = 0.f;
#pragma unroll
        for (int pass = 0; pass < 3; ++pass) {
            const uint32_t (*aq)[4] = (pass == 2) ? ql : qh;
            const __nv_bfloat16* B = (pass == 1) ? sKl : sKh;
#pragma unroll
            for (int kt = 0; kt < 4; ++kt)
#pragma unroll
                for (int nt = 0; nt < 8; ++nt) {
                    const __nv_bfloat16* bp = B + (nt * 8 + g) * KPITCH + kt * 16 + 2 * t4;
                    mma16816(s[nt], aq[kt], *(const uint32_t*)bp,
                             *(const uint32_t*)(bp + 8));
                }
        }
        // mask (window: r <= c < r + 1024)
#pragma unroll
        for (int nt = 0; nt < 8; ++nt) {
            int c0 = kstart + nt * 8 + 2 * t4;
            int c1 = c0 + 1;
            if (c0 < r0 || c0 >= r0 + WIN) s[nt][0] = -1e30f;
            if (c1 < r0 || c1 >= r0 + WIN) s[nt][1] = -1e30f;
            if (c0 < r0 + 8 || c0 >= r0 + 8 + WIN) s[nt][2] = -1e30f;
            if (c1 < r0 + 8 || c1 >= r0 + 8 + WIN) s[nt][3] = -1e30f;
        }
        // online softmax
        float ml0 = -1e30f, ml1 = -1e30f;
#pragma unroll
        for (int nt = 0; nt < 8; ++nt) {
            ml0 = fmaxf(ml0, fmaxf(s[nt][0], s[nt][1]));
            ml1 = fmaxf(ml1, fmaxf(s[nt][2], s[nt][3]));
        }
        ml0 = fmaxf(ml0, __shfl_xor_sync(0xffffffffu, ml0, 1));
        ml0 = fmaxf(ml0, __shfl_xor_sync(0xffffffffu, ml0, 2));
        ml1 = fmaxf(ml1, __shfl_xor_sync(0xffffffffu, ml1, 1));
        ml1 = fmaxf(ml1, __shfl_xor_sync(0xffffffffu, ml1, 2));
        float mn0 = fmaxf(mr0, ml0), mn1 = fmaxf(mr1, ml1);
        float al0 = __expf(mr0 - mn0), al1 = __expf(mr1 - mn1);
        mr0 = mn0; mr1 = mn1;
        float ps0 = 0.f, ps1 = 0.f;
#pragma unroll
        for (int nt = 0; nt < 8; ++nt) {
            s[nt][0] = __expf(s[nt][0] - mn0);
            s[nt][1] = __expf(s[nt][1] - mn0);
            s[nt][2] = __expf(s[nt][2] - mn1);
            s[nt][3] = __expf(s[nt][3] - mn1);
            ps0 += s[nt][0] + s[nt][1];
            ps1 += s[nt][2] + s[nt][3];
        }
        ps0 += __shfl_xor_sync(0xffffffffu, ps0, 1);
        ps0 += __shfl_xor_sync(0xffffffffu, ps0, 2);
        ps1 += __shfl_xor_sync(0xffffffffu, ps1, 1);
        ps1 += __shfl_xor_sync(0xffffffffu, ps1, 2);
        lr0 = lr0 * al0 + ps0;
        lr1 = lr1 * al1 + ps1;
#pragma unroll
        for (int nt = 0; nt < 8; ++nt) {
            accO[nt][0] *= al0; accO[nt][1] *= al0;
            accO[nt][2] *= al1; accO[nt][3] *= al1;
        }
        // P fragments (C layout -> A layout)
        uint32_t ph[4][4], pl[4][4];
#pragma unroll
        for (int kt = 0; kt < 4; ++kt) {
            float lx, ly;
            ph[kt][0] = pack_hi(s[2 * kt][0], s[2 * kt][1], lx, ly);
            pl[kt][0] = pack_lo(lx, ly);
            ph[kt][1] = pack_hi(s[2 * kt][2], s[2 * kt][3], lx, ly);
            pl[kt][1] = pack_lo(lx, ly);
            ph[kt][2] = pack_hi(s[2 * kt + 1][0], s[2 * kt + 1][1], lx, ly);
            pl[kt][2] = pack_lo(lx, ly);
            ph[kt][3] = pack_hi(s[2 * kt + 1][2], s[2 * kt + 1][3], lx, ly);
            pl[kt][3] = pack_lo(lx, ly);
        }
        // O += P V
#pragma unroll
        for (int pass = 0; pass < 3; ++pass) {
            const uint32_t (*ap)[4] = (pass == 2) ? pl : ph;
            const __nv_bfloat16* B = (pass == 1) ? sVl : sVh;
#pragma unroll
            for (int kt = 0; kt < 4; ++kt)
#pragma unroll
                for (int nt = 0; nt < 8; ++nt) {
                    const __nv_bfloat16* bp = B + (nt * 8 + g) * KPITCH + kt * 16 + 2 * t4;
                    mma16816(accO[nt], ap[kt], *(const uint32_t*)bp,
                             *(const uint32_t*)(bp + 8));
                }
        }
        __syncthreads();
    }

    float i0 = 1.f / lr0, i1 = 1.f / lr1;
#pragma unroll
    for (int nt = 0; nt < 8; ++nt) {
        size_t c = (size_t)n * HD + nt * 8 + 2 * t4;
        float2 v0 = make_float2(accO[nt][0] * i0, accO[nt][1] * i0);
        float2 v1 = make_float2(accO[nt][2] * i1, accO[nt][3] * i1);
        *(float2*)(Og + (size_t)r0 * EMB + c)       = v0;
        *(float2*)(Og + (size_t)(r0 + 8) * EMB + c) = v1;
    }
}

__global__ void copy_kv(const float* __restrict__ K, const float* __restrict__ V,
                        float* __restrict__ ok, float* __restrict__ ov)
{
    int i = blockIdx.x * blockDim.x + threadIdx.x;
    if (i < CLM1 * EMB) {
        size_t src = (size_t)(S_LEN - CLM1) * EMB + i;
        ok[i] = K[src];
        ov[i] = V[src];
    }
}

extern "C" void kernel_launch(void* const* d_in, const int* in_sizes, int n_in,
                              void* d_out, int out_size)
{
    (void)in_sizes; (void)n_in; (void)out_size;
    const float* x  = (const float*)d_in[0];
    const float* Wq = (const float*)d_in[1];
    const float* bq = (const float*)d_in[2];
    const float* Wk = (const float*)d_in[3];
    const float* bk = (const float*)d_in[4];
    const float* Wv = (const float*)d_in[5];
    const float* bv = (const float*)d_in[6];
    const float* Wo = (const float*)d_in[7];
    const float* bo = (const float*)d_in[8];
    const float* kc = (const float*)d_in[9];
    const float* vc = (const float*)d_in[10];
    const int*  pos = (const int*)d_in[11];
    float* out = (float*)d_out;

    float *Q, *K, *V, *O;
    cudaGetSymbolAddress((void**)&Q, g_Q);
    cudaGetSymbolAddress((void**)&K, g_K);
    cudaGetSymbolAddress((void**)&V, g_V);
    cudaGetSymbolAddress((void**)&O, g_O);
    __nv_bfloat16 *Qh, *Ql, *KH, *KL, *VH, *VL;
    cudaGetSymbolAddress((void**)&Qh, g_Qh);
    cudaGetSymbolAddress((void**)&Ql, g_Ql);
    cudaGetSymbolAddress((void**)&KH, g_KH);
    cudaGetSymbolAddress((void**)&KL, g_KL);
    cudaGetSymbolAddress((void**)&VH, g_VH);
    cudaGetSymbolAddress((void**)&VL, g_VL);

    gemm_mma<<<dim3(EMB / 128, S_LEN / 128, 3), 256>>>(
        x, Wq, Wk, Wv, bq, bk, bv, Q, K, V);

    rope_qk<<<(S_LEN * NH * (HD / 2) + 255) / 256, 256>>>(Q, K, pos);

    prep_q<<<(S_LEN * EMB / 4 + 255) / 256, 256>>>(Q, Qh, Ql);
    prep_kv<<<(KVROWS * EMB / 4 + 255) / 256, 256>>>(K, V, kc, vc, KH, KL, VH, VL);

    attn_mma<<<dim3(S_LEN / 64, NH), 128>>>(Qh, Ql, KH, KL, VH, VL, O);

    gemm_mma<<<dim3(EMB / 128, S_LEN / 128, 1), 256>>>(
        O, Wo, Wo, Wo, bo, bo, bo, out, out, out);

    copy_kv<<<(CLM1 * EMB + 255) / 256, 256>>>(
        K, V, out + (size_t)S_LEN * EMB,
        out + (size_t)S_LEN * EMB + (size_t)CLM1 * EMB);
}

// round 5
// speedup vs baseline: 2.8315x; 1.1341x over previous
#include <cuda_runtime.h>
#include <cuda_bf16.h>
#include <math.h>
#include <stdint.h>

#define S_LEN 2048
#define EMB   1024
#define NH    16
#define HD    64
#define CLM1  1023
#define INDIM (S_LEN + CLM1)   // 3071
#define KVROWS 3072
#define WIN   1024

// Scratch (allocation-free rule: device globals)
__device__ float g_Q[S_LEN * EMB];
__device__ float g_K[S_LEN * EMB];
__device__ float g_V[S_LEN * EMB];
__device__ __nv_bfloat16 g_Qh[S_LEN * EMB];
__device__ __nv_bfloat16 g_Ql[S_LEN * EMB];
__device__ __nv_bfloat16 g_Oh[S_LEN * EMB];
__device__ __nv_bfloat16 g_Ol[S_LEN * EMB];
__device__ __nv_bfloat16 g_KH[KVROWS * EMB];
__device__ __nv_bfloat16 g_KL[KVROWS * EMB];
__device__ __nv_bfloat16 g_VH[KVROWS * EMB];
__device__ __nv_bfloat16 g_VL[KVROWS * EMB];
__device__ __nv_bfloat16 g_Wh[4 * EMB * EMB];
__device__ __nv_bfloat16 g_Wl[4 * EMB * EMB];
__device__ __nv_bfloat16 g_xh[S_LEN * EMB];
__device__ __nv_bfloat16 g_xl[S_LEN * EMB];

// ---------------------------------------------------------------------------
// helpers
// ---------------------------------------------------------------------------
__device__ __forceinline__ void mma16816(
    float c[4], const uint32_t a[4], uint32_t b0, uint32_t b1)
{
    asm volatile(
        "mma.sync.aligned.m16n8k16.row.col.f32.bf16.bf16.f32 "
        "{%0,%1,%2,%3}, {%4,%5,%6,%7}, {%8,%9}, {%0,%1,%2,%3};"
        : "+f"(c[0]), "+f"(c[1]), "+f"(c[2]), "+f"(c[3])
        : "r"(a[0]), "r"(a[1]), "r"(a[2]), "r"(a[3]), "r"(b0), "r"(b1));
}
__device__ __forceinline__ uint32_t pack_hi(float x, float y,
                                            float& lx, float& ly)
{
    __nv_bfloat16 hx = __float2bfloat16(x);
    __nv_bfloat16 hy = __float2bfloat16(y);
    lx = x - __bfloat162float(hx);
    ly = y - __bfloat162float(hy);
    __nv_bfloat162 h2(hx, hy);
    return *reinterpret_cast<uint32_t*>(&h2);
}
__device__ __forceinline__ uint32_t pack_lo(float lx, float ly)
{
    __nv_bfloat162 l2(__float2bfloat16(lx), __float2bfloat16(ly));
    return *reinterpret_cast<uint32_t*>(&l2);
}
__device__ __forceinline__ uint32_t sptr(const void* p)
{
    return (uint32_t)__cvta_generic_to_shared(p);
}
__device__ __forceinline__ void ldx4(uint32_t r[4], uint32_t a)
{
    asm volatile("ldmatrix.sync.aligned.m8n8.x4.shared.b16 {%0,%1,%2,%3}, [%4];"
        : "=r"(r[0]), "=r"(r[1]), "=r"(r[2]), "=r"(r[3]) : "r"(a));
}
__device__ __forceinline__ void ldx4t(uint32_t r[4], uint32_t a)
{
    asm volatile("ldmatrix.sync.aligned.m8n8.x4.trans.shared.b16 {%0,%1,%2,%3}, [%4];"
        : "=r"(r[0]), "=r"(r[1]), "=r"(r[2]), "=r"(r[3]) : "r"(a));
}
#define CP16(s, g) \
    asm volatile("cp.async.cg.shared.global [%0], [%1], 16;" :: "r"(s), "l"(g))
#define CP_COMMIT() asm volatile("cp.async.commit_group;")
#define CP_WAIT1()  asm volatile("cp.async.wait_group 1;")
#define CP_WAIT0()  asm volatile("cp.async.wait_group 0;")

// ---------------------------------------------------------------------------
// split fp32 sources into bf16 hi/lo (weights x4 and x)
// ---------------------------------------------------------------------------
__global__ void split_all(
    const float* __restrict__ W0, const float* __restrict__ W1,
    const float* __restrict__ W2, const float* __restrict__ W3,
    const float* __restrict__ x,
    __nv_bfloat16* __restrict__ Wh, __nv_bfloat16* __restrict__ Wl,
    __nv_bfloat16* __restrict__ xh, __nv_bfloat16* __restrict__ xl)
{
    int z = blockIdx.y;
    const float* src;
    __nv_bfloat16 *dh, *dl;
    int n4;
    if (z < 4) {
        src = (z == 0) ? W0 : (z == 1) ? W1 : (z == 2) ? W2 : W3;
        dh = Wh + (size_t)z * EMB * EMB;
        dl = Wl + (size_t)z * EMB * EMB;
        n4 = EMB * EMB / 4;
    } else {
        src = x; dh = xh; dl = xl; n4 = S_LEN * EMB / 4;
    }
    int i = blockIdx.x * 256 + threadIdx.x;
    if (i >= n4) return;
    float4 v = ((const float4*)src)[i];
    float lx, ly, lz, lw;
    uint32_t h01 = pack_hi(v.x, v.y, lx, ly);
    uint32_t h23 = pack_hi(v.z, v.w, lz, lw);
    *(uint2*)(dh + (size_t)i * 4) = make_uint2(h01, h23);
    *(uint2*)(dl + (size_t)i * 4) = make_uint2(pack_lo(lx, ly), pack_lo(lz, lw));
}

// ---------------------------------------------------------------------------
// GEMM on pre-split bf16: C[M,1024] = A @ W^T + bias (3-pass hi/lo).
// 128x128 tile, BK=32, cp.async 2-stage, ldmatrix fragments.
// ---------------------------------------------------------------------------
#define GSTG 40960   // stage bytes: 4 tiles of 128x40 bf16
#define GAH 0
#define GAL 10240
#define GBH 20480
#define GBL 30720

__global__ __launch_bounds__(256) void gemm_bf(
    const __nv_bfloat16* __restrict__ Ah, const __nv_bfloat16* __restrict__ Al,
    const __nv_bfloat16* __restrict__ WhAll, const __nv_bfloat16* __restrict__ WlAll,
    int widx0,
    const float* __restrict__ b0p, const float* __restrict__ b1p, const float* __restrict__ b2p,
    float* __restrict__ C0, float* __restrict__ C1, float* __restrict__ C2)
{
    const int z = blockIdx.z;
    const __nv_bfloat16* Bh = WhAll + (size_t)(widx0 + z) * EMB * EMB;
    const __nv_bfloat16* Bl = WlAll + (size_t)(widx0 + z) * EMB * EMB;
    const float* bias = (z == 0) ? b0p : (z == 1) ? b1p : b2p;
    float*       C    = (z == 0) ? C0 : (z == 1) ? C1 : C2;

    extern __shared__ char dsm[];
    __shared__ float biass[128];

    const int t      = threadIdx.x;
    const int lane   = t & 31;
    const int wid    = t >> 5;
    const int warp_m = wid >> 1;
    const int warp_n = wid & 1;
    const int g      = lane >> 2;
    const int t4     = lane & 3;
    const int m0     = blockIdx.y * 128;
    const int n0     = blockIdx.x * 128;

    if (t < 128) biass[t] = bias[n0 + t];

    const int crow = t >> 2;     // 0..63 (plus 64 for i=1)
    const int cseg = t & 3;

    float acc[2][8][4];
#pragma unroll
    for (int mi = 0; mi < 2; ++mi)
#pragma unroll
        for (int ni = 0; ni < 8; ++ni)
#pragma unroll
            for (int j = 0; j < 4; ++j) acc[mi][ni][j] = 0.f;

    // issue chunk c into stage st
    auto issue = [&](int c, int st) {
        char* s = dsm + st * GSTG;
        int k0 = c * 32;
#pragma unroll
        for (int i = 0; i < 2; ++i) {
            int row = i * 64 + crow;
            size_t ga = (size_t)(m0 + row) * EMB + k0 + cseg * 8;
            size_t gb = (size_t)(n0 + row) * EMB + k0 + cseg * 8;
            uint32_t so = row * 80 + cseg * 16;
            CP16(sptr(s + GAH + so), Ah + ga);
            CP16(sptr(s + GAL + so), Al + ga);
            CP16(sptr(s + GBH + so), Bh + gb);
            CP16(sptr(s + GBL + so), Bl + gb);
        }
        CP_COMMIT();
    };

    issue(0, 0);
    for (int c = 0; c < 32; ++c) {
        if (c < 31) { issue(c + 1, (c + 1) & 1); CP_WAIT1(); }
        else        { CP_WAIT0(); }
        __syncthreads();

        char* s = dsm + (c & 1) * GSTG;
        // A fragments (hi+lo) for this chunk
        uint32_t aH[2][2][4], aL[2][2][4];
#pragma unroll
        for (int mi = 0; mi < 2; ++mi)
#pragma unroll
            for (int ks = 0; ks < 2; ++ks) {
                uint32_t ad = sptr(s + (warp_m * 32 + mi * 16 + (lane & 15)) * 80
                                     + (ks * 16 + ((lane >> 4) << 3)) * 2);
                ldx4(aH[mi][ks], ad + GAH);
                ldx4(aL[mi][ks], ad + GAL);
            }
#pragma unroll
        for (int pass = 0; pass < 3; ++pass) {
            const uint32_t (*A)[2][4] = (pass == 2) ? aL : aH;
            const uint32_t boff = (pass == 1) ? GBL : GBH;
#pragma unroll
            for (int ks = 0; ks < 2; ++ks) {
                uint32_t bf[4][4];
#pragma unroll
                for (int p = 0; p < 4; ++p)
                    ldx4(bf[p], sptr(s + boff
                         + (warp_n * 64 + p * 16 + (lane & 15)) * 80
                         + (ks * 16 + ((lane >> 4) << 3)) * 2));
#pragma unroll
                for (int mi = 0; mi < 2; ++mi)
#pragma unroll
                    for (int p = 0; p < 4; ++p) {
                        mma16816(acc[mi][2 * p],     A[mi][ks], bf[p][0], bf[p][2]);
                        mma16816(acc[mi][2 * p + 1], A[mi][ks], bf[p][1], bf[p][3]);
                    }
            }
        }
        __syncthreads();
    }

#pragma unroll
    for (int mi = 0; mi < 2; ++mi) {
        int r0 = m0 + warp_m * 32 + mi * 16 + g;
#pragma unroll
        for (int ni = 0; ni < 8; ++ni) {
            int cc = warp_n * 64 + ni * 8 + t4 * 2;
            float bx = biass[cc], by = biass[cc + 1];
            float2 v0 = make_float2(acc[mi][ni][0] + bx, acc[mi][ni][1] + by);
            float2 v1 = make_float2(acc[mi][ni][2] + bx, acc[mi][ni][3] + by);
            *(float2*)(C + (size_t)r0 * EMB + n0 + cc)       = v0;
            *(float2*)(C + (size_t)(r0 + 8) * EMB + n0 + cc) = v1;
        }
    }
}

// ---------------------------------------------------------------------------
// RoPE: reads Q,K fp32; writes Qh/Ql (scaled bf16 split) and K fp32 in-place
// ---------------------------------------------------------------------------
__global__ void rope_prep(const float* __restrict__ Qin, float* __restrict__ K,
                          const int* __restrict__ pos,
                          __nv_bfloat16* __restrict__ Qh, __nv_bfloat16* __restrict__ Ql)
{
    int idx = blockIdx.x * blockDim.x + threadIdx.x;
    if (idx >= S_LEN * NH * (HD / 2)) return;
    int d = idx & 31;
    int n = (idx >> 5) & 15;
    int s = idx >> 9;
    const float c = 0.28782313662425583f;   // ln(10000)/32
    float freq = expf(-(float)d * c);
    float ang  = __fmul_rn((float)(s + pos[0]), freq);
    float sn, cs;
    sincosf(ang, &sn, &cs);
    size_t base = (size_t)s * EMB + n * HD + 2 * d;
    float qe = Qin[base], qo = Qin[base + 1];
    float re = (qe * cs - qo * sn) * 0.125f;
    float ro = (qe * sn + qo * cs) * 0.125f;
    float lx, ly;
    uint32_t h = pack_hi(re, ro, lx, ly);
    *(uint32_t*)(Qh + base) = h;
    *(uint32_t*)(Ql + base) = pack_lo(lx, ly);
    float ke = K[base], ko = K[base + 1];
    K[base]     = ke * cs - ko * sn;
    K[base + 1] = ke * sn + ko * cs;
}

__global__ void prep_kv(const float* __restrict__ K, const float* __restrict__ V,
                        const float* __restrict__ kc, const float* __restrict__ vc,
                        __nv_bfloat16* __restrict__ KH, __nv_bfloat16* __restrict__ KL,
                        __nv_bfloat16* __restrict__ VH, __nv_bfloat16* __restrict__ VL)
{
    int i = blockIdx.x * blockDim.x + threadIdx.x;
    if (i >= KVROWS * EMB / 4) return;
    int kk = (i * 4) / EMB;
    int c  = (i * 4) % EMB;
    float4 kv = make_float4(0.f, 0.f, 0.f, 0.f);
    float4 vv = make_float4(0.f, 0.f, 0.f, 0.f);
    if (kk < CLM1) {
        kv = *(const float4*)(kc + (size_t)kk * EMB + c);
        vv = *(const float4*)(vc + (size_t)kk * EMB + c);
    } else if (kk < INDIM) {
        kv = *(const float4*)(K + (size_t)(kk - CLM1) * EMB + c);
        vv = *(const float4*)(V + (size_t)(kk - CLM1) * EMB + c);
    }
    float lx, ly, lz, lw;
    uint32_t h01 = pack_hi(kv.x, kv.y, lx, ly);
    uint32_t h23 = pack_hi(kv.z, kv.w, lz, lw);
    *(uint2*)(KH + (size_t)i * 4) = make_uint2(h01, h23);
    *(uint2*)(KL + (size_t)i * 4) = make_uint2(pack_lo(lx, ly), pack_lo(lz, lw));
    h01 = pack_hi(vv.x, vv.y, lx, ly);
    h23 = pack_hi(vv.z, vv.w, lz, lw);
    *(uint2*)(VH + (size_t)i * 4) = make_uint2(h01, h23);
    *(uint2*)(VL + (size_t)i * 4) = make_uint2(pack_lo(lx, ly), pack_lo(lz, lw));
}

// ---------------------------------------------------------------------------
// HMMA flash attention, cp.async 2-stage + ldmatrix(+trans for V).
// Block = (64 queries, head), 4 warps. Output written as bf16 hi/lo split.
// ---------------------------------------------------------------------------
#define ASTG 36864   // stage: 4 tiles of 64x72 bf16
#define AKH 0
#define AKL 9216
#define AVH 18432
#define AVL 27648

__global__ __launch_bounds__(128) void attn_mma(
    const __nv_bfloat16* __restrict__ Qh, const __nv_bfloat16* __restrict__ Ql,
    const __nv_bfloat16* __restrict__ KH, const __nv_bfloat16* __restrict__ KL,
    const __nv_bfloat16* __restrict__ VH, const __nv_bfloat16* __restrict__ VL,
    __nv_bfloat16* __restrict__ Oh, __nv_bfloat16* __restrict__ Ol)
{
    extern __shared__ char dsm[];
    const int t    = threadIdx.x;
    const int lane = t & 31;
    const int w    = t >> 5;
    const int g    = lane >> 2;
    const int t4   = lane & 3;
    const int n    = blockIdx.y;
    const int q0   = blockIdx.x * 64;
    const int r0   = q0 + w * 16 + g;

    const __nv_bfloat16* srcs[4] = { KH, KL, VH, VL };

    // persistent Q fragments
    uint32_t qh[4][4], ql[4][4];
#pragma unroll
    for (int kt = 0; kt < 4; ++kt) {
        size_t c = (size_t)n * HD + kt * 16 + 2 * t4;
        const __nv_bfloat16* p0 = Qh + (size_t)r0 * EMB + c;
        const __nv_bfloat16* p1 = Qh + (size_t)(r0 + 8) * EMB + c;
        qh[kt][0] = *(const uint32_t*)p0;
        qh[kt][1] = *(const uint32_t*)p1;
        qh[kt][2] = *(const uint32_t*)(p0 + 8);
        qh[kt][3] = *(const uint32_t*)(p1 + 8);
        p0 = Ql + (size_t)r0 * EMB + c;
        p1 = Ql + (size_t)(r0 + 8) * EMB + c;
        ql[kt][0] = *(const uint32_t*)p0;
        ql[kt][1] = *(const uint32_t*)p1;
        ql[kt][2] = *(const uint32_t*)(p0 + 8);
        ql[kt][3] = *(const uint32_t*)(p1 + 8);
    }

    float accO[8][4];
#pragma unroll
    for (int nt = 0; nt < 8; ++nt)
#pragma unroll
        for (int j = 0; j < 4; ++j) accO[nt][j] = 0.f;
    float mr0 = -1e30f, mr1 = -1e30f, lr0 = 0.f, lr1 = 0.f;

    auto issue = [&](int kb, int st) {
        char* s = dsm + st * ASTG;
        int kstart = q0 + kb * 64;
        int row_b = t >> 3, seg = t & 7;
#pragma unroll
        for (int i = 0; i < 16; ++i) {
            int tile = i >> 2;
            int row = (i & 3) * 16 + row_b;
            size_t go = (size_t)(kstart + row) * EMB + n * HD + seg * 8;
            CP16(sptr(s + tile * 9216 + row * 144 + seg * 16), srcs[tile] + go);
        }
        CP_COMMIT();
    };

    issue(0, 0);
    for (int kb = 0; kb < 17; ++kb) {
        if (kb < 16) { issue(kb + 1, (kb + 1) & 1); CP_WAIT1(); }
        else         { CP_WAIT0(); }
        __syncthreads();
        char* s = dsm + (kb & 1) * ASTG;
        const int kstart = q0 + kb * 64;

        // S = Q K^T
        float sc[8][4];
#pragma unroll
        for (int nt = 0; nt < 8; ++nt)
#pragma unroll
            for (int j = 0; j < 4; ++j) sc[nt][j] = 0.f;
#pragma unroll
        for (int pass = 0; pass < 3; ++pass) {
            const uint32_t (*aq)[4] = (pass == 2) ? ql : qh;
            const uint32_t koff = (pass == 1) ? AKL : AKH;
#pragma unroll
            for (int kt = 0; kt < 4; ++kt)
#pragma unroll
                for (int p = 0; p < 4; ++p) {
                    uint32_t kf[4];
                    ldx4(kf, sptr(s + koff + (p * 16 + (lane & 15)) * 144
                                 + (kt * 16 + ((lane >> 4) << 3)) * 2));
                    mma16816(sc[2 * p],     aq[kt], kf[0], kf[2]);
                    mma16816(sc[2 * p + 1], aq[kt], kf[1], kf[3]);
                }
        }
        // mask
#pragma unroll
        for (int nt = 0; nt < 8; ++nt) {
            int c0 = kstart + nt * 8 + 2 * t4;
            int c1 = c0 + 1;
            if (c0 < r0 || c0 >= r0 + WIN) sc[nt][0] = -1e30f;
            if (c1 < r0 || c1 >= r0 + WIN) sc[nt][1] = -1e30f;
            if (c0 < r0 + 8 || c0 >= r0 + 8 + WIN) sc[nt][2] = -1e30f;
            if (c1 < r0 + 8 || c1 >= r0 + 8 + WIN) sc[nt][3] = -1e30f;
        }
        // online softmax
        float ml0 = -1e30f, ml1 = -1e30f;
#pragma unroll
        for (int nt = 0; nt < 8; ++nt) {
            ml0 = fmaxf(ml0, fmaxf(sc[nt][0], sc[nt][1]));
            ml1 = fmaxf(ml1, fmaxf(sc[nt][2], sc[nt][3]));
        }
        ml0 = fmaxf(ml0, __shfl_xor_sync(0xffffffffu, ml0, 1));
        ml0 = fmaxf(ml0, __shfl_xor_sync(0xffffffffu, ml0, 2));
        ml1 = fmaxf(ml1, __shfl_xor_sync(0xffffffffu, ml1, 1));
        ml1 = fmaxf(ml1, __shfl_xor_sync(0xffffffffu, ml1, 2));
        float mn0 = fmaxf(mr0, ml0), mn1 = fmaxf(mr1, ml1);
        float al0 = __expf(mr0 - mn0), al1 = __expf(mr1 - mn1);
        mr0 = mn0; mr1 = mn1;
        float ps0 = 0.f, ps1 = 0.f;
#pragma unroll
        for (int nt = 0; nt < 8; ++nt) {
            sc[nt][0] = __expf(sc[nt][0] - mn0);
            sc[nt][1] = __expf(sc[nt][1] - mn0);
            sc[nt][2] = __expf(sc[nt][2] - mn1);
            sc[nt][3] = __expf(sc[nt][3] - mn1);
            ps0 += sc[nt][0] + sc[nt][1];
            ps1 += sc[nt][2] + sc[nt][3];
        }
        ps0 += __shfl_xor_sync(0xffffffffu, ps0, 1);
        ps0 += __shfl_xor_sync(0xffffffffu, ps0, 2);
        ps1 += __shfl_xor_sync(0xffffffffu, ps1, 1);
        ps1 += __shfl_xor_sync(0xffffffffu, ps1, 2);
        lr0 = lr0 * al0 + ps0;
        lr1 = lr1 * al1 + ps1;
#pragma unroll
        for (int nt = 0; nt < 8; ++nt) {
            accO[nt][0] *= al0; accO[nt][1] *= al0;
            accO[nt][2] *= al1; accO[nt][3] *= al1;
        }
        // P fragments
        uint32_t ph[4][4], pl[4][4];
#pragma unroll
        for (int kt = 0; kt < 4; ++kt) {
            float lx, ly;
            ph[kt][0] = pack_hi(sc[2 * kt][0], sc[2 * kt][1], lx, ly);
            pl[kt][0] = pack_lo(lx, ly);
            ph[kt][1] = pack_hi(sc[2 * kt][2], sc[2 * kt][3], lx, ly);
            pl[kt][1] = pack_lo(lx, ly);
            ph[kt][2] = pack_hi(sc[2 * kt + 1][0], sc[2 * kt + 1][1], lx, ly);
            pl[kt][2] = pack_lo(lx, ly);
            ph[kt][3] = pack_hi(sc[2 * kt + 1][2], sc[2 * kt + 1][3], lx, ly);
            pl[kt][3] = pack_lo(lx, ly);
        }
        // O += P V  (V via ldmatrix.trans, no smem transpose)
#pragma unroll
        for (int pass = 0; pass < 3; ++pass) {
            const uint32_t (*ap)[4] = (pass == 2) ? pl : ph;
            const uint32_t voff = (pass == 1) ? AVL : AVH;
#pragma unroll
            for (int kt = 0; kt < 4; ++kt)
#pragma unroll
                for (int p = 0; p < 4; ++p) {
                    uint32_t vf[4];
                    ldx4t(vf, sptr(s + voff + (kt * 16 + (lane & 15)) * 144
                                  + (p * 16 + ((lane >> 4) << 3)) * 2));
                    mma16816(accO[2 * p],     ap[kt], vf[0], vf[1]);
                    mma16816(accO[2 * p + 1], ap[kt], vf[2], vf[3]);
                }
        }
        __syncthreads();
    }

    float i0 = 1.f / lr0, i1 = 1.f / lr1;
#pragma unroll
    for (int nt = 0; nt < 8; ++nt) {
        size_t c = (size_t)n * HD + nt * 8 + 2 * t4;
        float lx, ly;
        uint32_t h0 = pack_hi(accO[nt][0] * i0, accO[nt][1] * i0, lx, ly);
        uint32_t l0 = pack_lo(lx, ly);
        uint32_t h1 = pack_hi(accO[nt][2] * i1, accO[nt][3] * i1, lx, ly);
        uint32_t l1 = pack_lo(lx, ly);
        *(uint32_t*)(Oh + (size_t)r0 * EMB + c)       = h0;
        *(uint32_t*)(Ol + (size_t)r0 * EMB + c)       = l0;
        *(uint32_t*)(Oh + (size_t)(r0 + 8) * EMB + c) = h1;
        *(uint32_t*)(Ol + (size_t)(r0 + 8) * EMB + c) = l1;
    }
}

__global__ void copy_kv(const float* __restrict__ K, const float* __restrict__ V,
                        float* __restrict__ ok, float* __restrict__ ov)
{
    int i = blockIdx.x * blockDim.x + threadIdx.x;
    if (i < CLM1 * EMB) {
        size_t src = (size_t)(S_LEN - CLM1) * EMB + i;
        ok[i] = K[src];
        ov[i] = V[src];
    }
}

extern "C" void kernel_launch(void* const* d_in, const int* in_sizes, int n_in,
                              void* d_out, int out_size)
{
    (void)in_sizes; (void)n_in; (void)out_size;
    const float* x  = (const float*)d_in[0];
    const float* Wq = (const float*)d_in[1];
    const float* bq = (const float*)d_in[2];
    const float* Wk = (const float*)d_in[3];
    const float* bk = (const float*)d_in[4];
    const float* Wv = (const float*)d_in[5];
    const float* bv = (const float*)d_in[6];
    const float* Wo = (const float*)d_in[7];
    const float* bo = (const float*)d_in[8];
    const float* kc = (const float*)d_in[9];
    const float* vc = (const float*)d_in[10];
    const int*  pos = (const int*)d_in[11];
    float* out = (float*)d_out;

    float *Q, *K, *V;
    cudaGetSymbolAddress((void**)&Q, g_Q);
    cudaGetSymbolAddress((void**)&K, g_K);
    cudaGetSymbolAddress((void**)&V, g_V);
    __nv_bfloat16 *Qh, *Ql, *Oh, *Ol, *KH, *KL, *VH, *VL, *Wh, *Wl, *xh, *xl;
    cudaGetSymbolAddress((void**)&Qh, g_Qh);
    cudaGetSymbolAddress((void**)&Ql, g_Ql);
    cudaGetSymbolAddress((void**)&Oh, g_Oh);
    cudaGetSymbolAddress((void**)&Ol, g_Ol);
    cudaGetSymbolAddress((void**)&KH, g_KH);
    cudaGetSymbolAddress((void**)&KL, g_KL);
    cudaGetSymbolAddress((void**)&VH, g_VH);
    cudaGetSymbolAddress((void**)&VL, g_VL);
    cudaGetSymbolAddress((void**)&Wh, g_Wh);
    cudaGetSymbolAddress((void**)&Wl, g_Wl);
    cudaGetSymbolAddress((void**)&xh, g_xh);
    cudaGetSymbolAddress((void**)&xl, g_xl);

    cudaFuncSetAttribute(gemm_bf,
        cudaFuncAttributeMaxDynamicSharedMemorySize, 2 * GSTG);
    cudaFuncSetAttribute(attn_mma,
        cudaFuncAttributeMaxDynamicSharedMemorySize, 2 * ASTG);

    // 1. split weights + x
    split_all<<<dim3(S_LEN * EMB / 4 / 256, 5), 256>>>(
        Wq, Wk, Wv, Wo, x, Wh, Wl, xh, xl);

    // 2. QKV projections (z = 0,1,2)
    gemm_bf<<<dim3(EMB / 128, S_LEN / 128, 3), 256, 2 * GSTG>>>(
        xh, xl, Wh, Wl, 0, bq, bk, bv, Q, K, V);

    // 3. RoPE (+ Q split)
    rope_prep<<<(S_LEN * NH * (HD / 2) + 255) / 256, 256>>>(Q, K, pos, Qh, Ql);

    // 4. concat + split K/V
    prep_kv<<<(KVROWS * EMB / 4 + 255) / 256, 256>>>(K, V, kc, vc, KH, KL, VH, VL);

    // 5. attention (writes split O)
    attn_mma<<<dim3(S_LEN / 64, NH), 128, 2 * ASTG>>>(
        Qh, Ql, KH, KL, VH, VL, Oh, Ol);

    // 6. output projection (W index 3)
    gemm_bf<<<dim3(EMB / 128, S_LEN / 128, 1), 256, 2 * GSTG>>>(
        Oh, Ol, Wh, Wl, 3, bo, bo, bo, out, out, out);

    // 7. new_k / new_v
    copy_kv<<<(CLM1 * EMB + 255) / 256, 256>>>(
        K, V, out + (size_t)S_LEN * EMB,
        out + (size_t)S_LEN * EMB + (size_t)CLM1 * EMB);
}

// round 6
// speedup vs baseline: 2.8809x; 1.0175x over previous
#include <cuda_runtime.h>
#include <cuda_bf16.h>
#include <math.h>
#include <stdint.h>

#define S_LEN 2048
#define EMB   1024
#define NH    16
#define HD    64
#define CLM1  1023
#define INDIM (S_LEN + CLM1)   // 3071
#define KVROWS 3072
#define WIN   1024

// Scratch (allocation-free rule: device globals)
__device__ float g_Q[S_LEN * EMB];
__device__ float g_K[S_LEN * EMB];
__device__ float g_V[S_LEN * EMB];
__device__ __nv_bfloat16 g_Qh[S_LEN * EMB];
__device__ __nv_bfloat16 g_Ql[S_LEN * EMB];
__device__ __nv_bfloat16 g_Oh[S_LEN * EMB];
__device__ __nv_bfloat16 g_Ol[S_LEN * EMB];
__device__ __nv_bfloat16 g_KH[KVROWS * EMB];
__device__ __nv_bfloat16 g_KL[KVROWS * EMB];
__device__ __nv_bfloat16 g_VH[KVROWS * EMB];
__device__ __nv_bfloat16 g_VL[KVROWS * EMB];
__device__ __nv_bfloat16 g_Wh[4 * EMB * EMB];
__device__ __nv_bfloat16 g_Wl[4 * EMB * EMB];
__device__ __nv_bfloat16 g_xh[S_LEN * EMB];
__device__ __nv_bfloat16 g_xl[S_LEN * EMB];

// ---------------------------------------------------------------------------
// helpers
// ---------------------------------------------------------------------------
__device__ __forceinline__ void mma16816(
    float c[4], const uint32_t a[4], uint32_t b0, uint32_t b1)
{
    asm volatile(
        "mma.sync.aligned.m16n8k16.row.col.f32.bf16.bf16.f32 "
        "{%0,%1,%2,%3}, {%4,%5,%6,%7}, {%8,%9}, {%0,%1,%2,%3};"
        : "+f"(c[0]), "+f"(c[1]), "+f"(c[2]), "+f"(c[3])
        : "r"(a[0]), "r"(a[1]), "r"(a[2]), "r"(a[3]), "r"(b0), "r"(b1));
}
__device__ __forceinline__ uint32_t pack_hi(float x, float y,
                                            float& lx, float& ly)
{
    __nv_bfloat16 hx = __float2bfloat16(x);
    __nv_bfloat16 hy = __float2bfloat16(y);
    lx = x - __bfloat162float(hx);
    ly = y - __bfloat162float(hy);
    __nv_bfloat162 h2(hx, hy);
    return *reinterpret_cast<uint32_t*>(&h2);
}
__device__ __forceinline__ uint32_t pack_lo(float lx, float ly)
{
    __nv_bfloat162 l2(__float2bfloat16(lx), __float2bfloat16(ly));
    return *reinterpret_cast<uint32_t*>(&l2);
}
__device__ __forceinline__ uint32_t sptr(const void* p)
{
    return (uint32_t)__cvta_generic_to_shared(p);
}
__device__ __forceinline__ void ldx4(uint32_t r[4], uint32_t a)
{
    asm volatile("ldmatrix.sync.aligned.m8n8.x4.shared.b16 {%0,%1,%2,%3}, [%4];"
        : "=r"(r[0]), "=r"(r[1]), "=r"(r[2]), "=r"(r[3]) : "r"(a));
}
__device__ __forceinline__ void ldx4t(uint32_t r[4], uint32_t a)
{
    asm volatile("ldmatrix.sync.aligned.m8n8.x4.trans.shared.b16 {%0,%1,%2,%3}, [%4];"
        : "=r"(r[0]), "=r"(r[1]), "=r"(r[2]), "=r"(r[3]) : "r"(a));
}
#define CP16(s, g) \
    asm volatile("cp.async.cg.shared.global [%0], [%1], 16;" :: "r"(s), "l"(g))
#define CP_COMMIT() asm volatile("cp.async.commit_group;")
#define CP_WAIT2()  asm volatile("cp.async.wait_group 2;")
#define CP_WAIT1()  asm volatile("cp.async.wait_group 1;")
#define CP_WAIT0()  asm volatile("cp.async.wait_group 0;")

// ---------------------------------------------------------------------------
// split fp32 sources into bf16 hi/lo (weights x4 and x)
// ---------------------------------------------------------------------------
__global__ void split_all(
    const float* __restrict__ W0, const float* __restrict__ W1,
    const float* __restrict__ W2, const float* __restrict__ W3,
    const float* __restrict__ x,
    __nv_bfloat16* __restrict__ Wh, __nv_bfloat16* __restrict__ Wl,
    __nv_bfloat16* __restrict__ xh, __nv_bfloat16* __restrict__ xl)
{
    int z = blockIdx.y;
    const float* src;
    __nv_bfloat16 *dh, *dl;
    int n4;
    if (z < 4) {
        src = (z == 0) ? W0 : (z == 1) ? W1 : (z == 2) ? W2 : W3;
        dh = Wh + (size_t)z * EMB * EMB;
        dl = Wl + (size_t)z * EMB * EMB;
        n4 = EMB * EMB / 4;
    } else {
        src = x; dh = xh; dl = xl; n4 = S_LEN * EMB / 4;
    }
    int i = blockIdx.x * 256 + threadIdx.x;
    if (i >= n4) return;
    float4 v = ((const float4*)src)[i];
    float lx, ly, lz, lw;
    uint32_t h01 = pack_hi(v.x, v.y, lx, ly);
    uint32_t h23 = pack_hi(v.z, v.w, lz, lw);
    *(uint2*)(dh + (size_t)i * 4) = make_uint2(h01, h23);
    *(uint2*)(dl + (size_t)i * 4) = make_uint2(pack_lo(lx, ly), pack_lo(lz, lw));
}

// ---------------------------------------------------------------------------
// GEMM on pre-split bf16: 128x128 tile, BK=32, 3-stage cp.async, ldmatrix.
// ---------------------------------------------------------------------------
#define GSTG 40960
#define GAH 0
#define GAL 10240
#define GBH 20480
#define GBL 30720

__global__ __launch_bounds__(256) void gemm_bf(
    const __nv_bfloat16* __restrict__ Ah, const __nv_bfloat16* __restrict__ Al,
    const __nv_bfloat16* __restrict__ WhAll, const __nv_bfloat16* __restrict__ WlAll,
    int widx0,
    const float* __restrict__ b0p, const float* __restrict__ b1p, const float* __restrict__ b2p,
    float* __restrict__ C0, float* __restrict__ C1, float* __restrict__ C2)
{
    const int z = blockIdx.z;
    const __nv_bfloat16* Bh = WhAll + (size_t)(widx0 + z) * EMB * EMB;
    const __nv_bfloat16* Bl = WlAll + (size_t)(widx0 + z) * EMB * EMB;
    const float* bias = (z == 0) ? b0p : (z == 1) ? b1p : b2p;
    float*       C    = (z == 0) ? C0 : (z == 1) ? C1 : C2;

    extern __shared__ char dsm[];
    __shared__ float biass[128];

    const int t      = threadIdx.x;
    const int lane   = t & 31;
    const int wid    = t >> 5;
    const int warp_m = wid >> 1;
    const int warp_n = wid & 1;
    const int g      = lane >> 2;
    const int t4     = lane & 3;
    const int m0     = blockIdx.y * 128;
    const int n0     = blockIdx.x * 128;

    if (t < 128) biass[t] = bias[n0 + t];

    const int crow = t >> 2;
    const int cseg = t & 3;

    float acc[2][8][4];
#pragma unroll
    for (int mi = 0; mi < 2; ++mi)
#pragma unroll
        for (int ni = 0; ni < 8; ++ni)
#pragma unroll
            for (int j = 0; j < 4; ++j) acc[mi][ni][j] = 0.f;

    auto issue = [&](int c, int st) {
        char* s = dsm + st * GSTG;
        int k0 = c * 32;
#pragma unroll
        for (int i = 0; i < 2; ++i) {
            int row = i * 64 + crow;
            size_t ga = (size_t)(m0 + row) * EMB + k0 + cseg * 8;
            size_t gb = (size_t)(n0 + row) * EMB + k0 + cseg * 8;
            uint32_t so = row * 80 + cseg * 16;
            CP16(sptr(s + GAH + so), Ah + ga);
            CP16(sptr(s + GAL + so), Al + ga);
            CP16(sptr(s + GBH + so), Bh + gb);
            CP16(sptr(s + GBL + so), Bl + gb);
        }
        CP_COMMIT();
    };

    issue(0, 0);
    issue(1, 1);
    for (int c = 0; c < 32; ++c) {
        if (c < 30)      { issue(c + 2, (c + 2) % 3); CP_WAIT2(); }
        else if (c == 30){ CP_WAIT1(); }
        else             { CP_WAIT0(); }
        __syncthreads();

        char* s = dsm + (c % 3) * GSTG;
        uint32_t aH[2][2][4], aL[2][2][4];
#pragma unroll
        for (int mi = 0; mi < 2; ++mi)
#pragma unroll
            for (int ks = 0; ks < 2; ++ks) {
                uint32_t ad = sptr(s + (warp_m * 32 + mi * 16 + (lane & 15)) * 80
                                     + (ks * 16 + ((lane >> 4) << 3)) * 2);
                ldx4(aH[mi][ks], ad + GAH);
                ldx4(aL[mi][ks], ad + GAL);
            }
#pragma unroll
        for (int pass = 0; pass < 3; ++pass) {
            const uint32_t (*A)[2][4] = (pass == 2) ? aL : aH;
            const uint32_t boff = (pass == 1) ? GBL : GBH;
#pragma unroll
            for (int ks = 0; ks < 2; ++ks) {
                uint32_t bf[4][4];
#pragma unroll
                for (int p = 0; p < 4; ++p)
                    ldx4(bf[p], sptr(s + boff
                         + (warp_n * 64 + p * 16 + (lane & 15)) * 80
                         + (ks * 16 + ((lane >> 4) << 3)) * 2));
#pragma unroll
                for (int mi = 0; mi < 2; ++mi)
#pragma unroll
                    for (int p = 0; p < 4; ++p) {
                        mma16816(acc[mi][2 * p],     A[mi][ks], bf[p][0], bf[p][2]);
                        mma16816(acc[mi][2 * p + 1], A[mi][ks], bf[p][1], bf[p][3]);
                    }
            }
        }
        __syncthreads();
    }

#pragma unroll
    for (int mi = 0; mi < 2; ++mi) {
        int r0 = m0 + warp_m * 32 + mi * 16 + g;
#pragma unroll
        for (int ni = 0; ni < 8; ++ni) {
            int cc = warp_n * 64 + ni * 8 + t4 * 2;
            float bx = biass[cc], by = biass[cc + 1];
            float2 v0 = make_float2(acc[mi][ni][0] + bx, acc[mi][ni][1] + by);
            float2 v1 = make_float2(acc[mi][ni][2] + bx, acc[mi][ni][3] + by);
            *(float2*)(C + (size_t)r0 * EMB + n0 + cc)       = v0;
            *(float2*)(C + (size_t)(r0 + 8) * EMB + n0 + cc) = v1;
        }
    }
}

// ---------------------------------------------------------------------------
// RoPE: reads Q,K fp32; writes Qh/Ql (scaled bf16 split) and K fp32 in-place
// ---------------------------------------------------------------------------
__global__ void rope_prep(const float* __restrict__ Qin, float* __restrict__ K,
                          const int* __restrict__ pos,
                          __nv_bfloat16* __restrict__ Qh, __nv_bfloat16* __restrict__ Ql)
{
    int idx = blockIdx.x * blockDim.x + threadIdx.x;
    if (idx >= S_LEN * NH * (HD / 2)) return;
    int d = idx & 31;
    int n = (idx >> 5) & 15;
    int s = idx >> 9;
    const float c = 0.28782313662425583f;
    float freq = expf(-(float)d * c);
    float ang  = __fmul_rn((float)(s + pos[0]), freq);
    float sn, cs;
    sincosf(ang, &sn, &cs);
    size_t base = (size_t)s * EMB + n * HD + 2 * d;
    float qe = Qin[base], qo = Qin[base + 1];
    float re = (qe * cs - qo * sn) * 0.125f;
    float ro = (qe * sn + qo * cs) * 0.125f;
    float lx, ly;
    uint32_t h = pack_hi(re, ro, lx, ly);
    *(uint32_t*)(Qh + base) = h;
    *(uint32_t*)(Ql + base) = pack_lo(lx, ly);
    float ke = K[base], ko = K[base + 1];
    K[base]     = ke * cs - ko * sn;
    K[base + 1] = ke * sn + ko * cs;
}

// concat + split K/V; also emits new_k/new_v fp32 outputs (rows >= S_LEN)
__global__ void prep_kv(const float* __restrict__ K, const float* __restrict__ V,
                        const float* __restrict__ kc, const float* __restrict__ vc,
                        __nv_bfloat16* __restrict__ KH, __nv_bfloat16* __restrict__ KL,
                        __nv_bfloat16* __restrict__ VH, __nv_bfloat16* __restrict__ VL,
                        float* __restrict__ ok, float* __restrict__ ov)
{
    int i = blockIdx.x * blockDim.x + threadIdx.x;
    if (i >= KVROWS * EMB / 4) return;
    int kk = (i * 4) / EMB;
    int c  = (i * 4) % EMB;
    float4 kv = make_float4(0.f, 0.f, 0.f, 0.f);
    float4 vv = make_float4(0.f, 0.f, 0.f, 0.f);
    if (kk < CLM1) {
        kv = *(const float4*)(kc + (size_t)kk * EMB + c);
        vv = *(const float4*)(vc + (size_t)kk * EMB + c);
    } else if (kk < INDIM) {
        kv = *(const float4*)(K + (size_t)(kk - CLM1) * EMB + c);
        vv = *(const float4*)(V + (size_t)(kk - CLM1) * EMB + c);
    }
    if (kk >= S_LEN && kk < INDIM) {
        size_t o = (size_t)(kk - S_LEN) * EMB + c;
        *(float4*)(ok + o) = kv;
        *(float4*)(ov + o) = vv;
    }
    float lx, ly, lz, lw;
    uint32_t h01 = pack_hi(kv.x, kv.y, lx, ly);
    uint32_t h23 = pack_hi(kv.z, kv.w, lz, lw);
    *(uint2*)(KH + (size_t)i * 4) = make_uint2(h01, h23);
    *(uint2*)(KL + (size_t)i * 4) = make_uint2(pack_lo(lx, ly), pack_lo(lz, lw));
    h01 = pack_hi(vv.x, vv.y, lx, ly);
    h23 = pack_hi(vv.z, vv.w, lz, lw);
    *(uint2*)(VH + (size_t)i * 4) = make_uint2(h01, h23);
    *(uint2*)(VL + (size_t)i * 4) = make_uint2(pack_lo(lx, ly), pack_lo(lz, lw));
}

// ---------------------------------------------------------------------------
// HMMA flash attention. Block = (128 queries, head), 8 warps, 3-stage cp.async.
// K/V tiles 64x64 bf16, XOR-swizzled (conflict-free cp.async + ldmatrix).
// ---------------------------------------------------------------------------
#define ASTG 32768   // stage: 4 swizzled tiles of 64x64 bf16 (8KB each)
#define AKH 0
#define AKL 8192
#define AVH 16384
#define AVL 24576
#define NKB 18

__device__ __forceinline__ uint32_t swz(int row, int unit)
{
    return (uint32_t)(row * 128 + ((unit ^ (row & 7)) << 4));
}

__global__ __launch_bounds__(256) void attn_mma(
    const __nv_bfloat16* __restrict__ Qh, const __nv_bfloat16* __restrict__ Ql,
    const __nv_bfloat16* __restrict__ KH, const __nv_bfloat16* __restrict__ KL,
    const __nv_bfloat16* __restrict__ VH, const __nv_bfloat16* __restrict__ VL,
    __nv_bfloat16* __restrict__ Oh, __nv_bfloat16* __restrict__ Ol)
{
    extern __shared__ char dsm[];
    const int t    = threadIdx.x;
    const int lane = t & 31;
    const int w    = t >> 5;
    const int g    = lane >> 2;
    const int t4   = lane & 3;
    const int n    = blockIdx.y;
    const int q0   = blockIdx.x * 128;
    const int r0   = q0 + w * 16 + g;

    const __nv_bfloat16* srcs[4] = { KH, KL, VH, VL };

    // persistent Q fragments
    uint32_t qh[4][4], ql[4][4];
#pragma unroll
    for (int kt = 0; kt < 4; ++kt) {
        size_t c = (size_t)n * HD + kt * 16 + 2 * t4;
        const __nv_bfloat16* p0 = Qh + (size_t)r0 * EMB + c;
        const __nv_bfloat16* p1 = Qh + (size_t)(r0 + 8) * EMB + c;
        qh[kt][0] = *(const uint32_t*)p0;
        qh[kt][1] = *(const uint32_t*)p1;
        qh[kt][2] = *(const uint32_t*)(p0 + 8);
        qh[kt][3] = *(const uint32_t*)(p1 + 8);
        p0 = Ql + (size_t)r0 * EMB + c;
        p1 = Ql + (size_t)(r0 + 8) * EMB + c;
        ql[kt][0] = *(const uint32_t*)p0;
        ql[kt][1] = *(const uint32_t*)p1;
        ql[kt][2] = *(const uint32_t*)(p0 + 8);
        ql[kt][3] = *(const uint32_t*)(p1 + 8);
    }

    float accO[8][4];
#pragma unroll
    for (int nt = 0; nt < 8; ++nt)
#pragma unroll
        for (int j = 0; j < 4; ++j) accO[nt][j] = 0.f;
    float mr0 = -1e30f, mr1 = -1e30f, lr0 = 0.f, lr1 = 0.f;

    // 256 threads load 4 tiles x 64 rows x 8 16B-units = 2048 -> 8 per thread
    auto issue = [&](int kb, int st) {
        char* s = dsm + st * ASTG;
        int kstart = q0 + kb * 64;
        int row_b = t >> 3, seg = t & 7;
#pragma unroll
        for (int i = 0; i < 8; ++i) {
            int tile = i >> 1;
            int row = (i & 1) * 32 + row_b;
            size_t go = (size_t)(kstart + row) * EMB + n * HD + seg * 8;
            CP16(sptr(s + tile * 8192 + swz(row, seg)), srcs[tile] + go);
        }
        CP_COMMIT();
    };

    issue(0, 0);
    issue(1, 1);
    for (int kb = 0; kb < NKB; ++kb) {
        if (kb < NKB - 2)       { issue(kb + 2, (kb + 2) % 3); CP_WAIT2(); }
        else if (kb == NKB - 2) { CP_WAIT1(); }
        else                    { CP_WAIT0(); }
        __syncthreads();
        char* s = dsm + (kb % 3) * ASTG;
        const int kstart = q0 + kb * 64;

        // S = Q K^T
        float sc[8][4];
#pragma unroll
        for (int nt = 0; nt < 8; ++nt)
#pragma unroll
            for (int j = 0; j < 4; ++j) sc[nt][j] = 0.f;
#pragma unroll
        for (int pass = 0; pass < 3; ++pass) {
            const uint32_t (*aq)[4] = (pass == 2) ? ql : qh;
            const uint32_t koff = (pass == 1) ? AKL : AKH;
#pragma unroll
            for (int kt = 0; kt < 4; ++kt)
#pragma unroll
                for (int p = 0; p < 4; ++p) {
                    uint32_t kf[4];
                    int row = p * 16 + (lane & 15);
                    int unit = kt * 2 + (lane >> 4);
                    ldx4(kf, sptr(s + koff + swz(row, unit)));
                    mma16816(sc[2 * p],     aq[kt], kf[0], kf[2]);
                    mma16816(sc[2 * p + 1], aq[kt], kf[1], kf[3]);
                }
        }
        // mask
#pragma unroll
        for (int nt = 0; nt < 8; ++nt) {
            int c0 = kstart + nt * 8 + 2 * t4;
            int c1 = c0 + 1;
            if (c0 < r0 || c0 >= r0 + WIN) sc[nt][0] = -1e30f;
            if (c1 < r0 || c1 >= r0 + WIN) sc[nt][1] = -1e30f;
            if (c0 < r0 + 8 || c0 >= r0 + 8 + WIN) sc[nt][2] = -1e30f;
            if (c1 < r0 + 8 || c1 >= r0 + 8 + WIN) sc[nt][3] = -1e30f;
        }
        // online softmax
        float ml0 = -1e30f, ml1 = -1e30f;
#pragma unroll
        for (int nt = 0; nt < 8; ++nt) {
            ml0 = fmaxf(ml0, fmaxf(sc[nt][0], sc[nt][1]));
            ml1 = fmaxf(ml1, fmaxf(sc[nt][2], sc[nt][3]));
        }
        ml0 = fmaxf(ml0, __shfl_xor_sync(0xffffffffu, ml0, 1));
        ml0 = fmaxf(ml0, __shfl_xor_sync(0xffffffffu, ml0, 2));
        ml1 = fmaxf(ml1, __shfl_xor_sync(0xffffffffu, ml1, 1));
        ml1 = fmaxf(ml1, __shfl_xor_sync(0xffffffffu, ml1, 2));
        float mn0 = fmaxf(mr0, ml0), mn1 = fmaxf(mr1, ml1);
        float al0 = __expf(mr0 - mn0), al1 = __expf(mr1 - mn1);
        mr0 = mn0; mr1 = mn1;
        float ps0 = 0.f, ps1 = 0.f;
#pragma unroll
        for (int nt = 0; nt < 8; ++nt) {
            sc[nt][0] = __expf(sc[nt][0] - mn0);
            sc[nt][1] = __expf(sc[nt][1] - mn0);
            sc[nt][2] = __expf(sc[nt][2] - mn1);
            sc[nt][3] = __expf(sc[nt][3] - mn1);
            ps0 += sc[nt][0] + sc[nt][1];
            ps1 += sc[nt][2] + sc[nt][3];
        }
        ps0 += __shfl_xor_sync(0xffffffffu, ps0, 1);
        ps0 += __shfl_xor_sync(0xffffffffu, ps0, 2);
        ps1 += __shfl_xor_sync(0xffffffffu, ps1, 1);
        ps1 += __shfl_xor_sync(0xffffffffu, ps1, 2);
        lr0 = lr0 * al0 + ps0;
        lr1 = lr1 * al1 + ps1;
#pragma unroll
        for (int nt = 0; nt < 8; ++nt) {
            accO[nt][0] *= al0; accO[nt][1] *= al0;
            accO[nt][2] *= al1; accO[nt][3] *= al1;
        }
        // P fragments
        uint32_t ph[4][4], pl[4][4];
#pragma unroll
        for (int kt = 0; kt < 4; ++kt) {
            float lx, ly;
            ph[kt][0] = pack_hi(sc[2 * kt][0], sc[2 * kt][1], lx, ly);
            pl[kt][0] = pack_lo(lx, ly);
            ph[kt][1] = pack_hi(sc[2 * kt][2], sc[2 * kt][3], lx, ly);
            pl[kt][1] = pack_lo(lx, ly);
            ph[kt][2] = pack_hi(sc[2 * kt + 1][0], sc[2 * kt + 1][1], lx, ly);
            pl[kt][2] = pack_lo(lx, ly);
            ph[kt][3] = pack_hi(sc[2 * kt + 1][2], sc[2 * kt + 1][3], lx, ly);
            pl[kt][3] = pack_lo(lx, ly);
        }
        // O += P V  (ldmatrix.trans on row-major V)
#pragma unroll
        for (int pass = 0; pass < 3; ++pass) {
            const uint32_t (*ap)[4] = (pass == 2) ? pl : ph;
            const uint32_t voff = (pass == 1) ? AVL : AVH;
#pragma unroll
            for (int kt = 0; kt < 4; ++kt)
#pragma unroll
                for (int p = 0; p < 4; ++p) {
                    uint32_t vf[4];
                    int row = kt * 16 + (lane & 15);
                    int unit = p * 2 + (lane >> 4);
                    ldx4t(vf, sptr(s + voff + swz(row, unit)));
                    mma16816(accO[2 * p],     ap[kt], vf[0], vf[1]);
                    mma16816(accO[2 * p + 1], ap[kt], vf[2], vf[3]);
                }
        }
        __syncthreads();
    }

    float i0 = 1.f / lr0, i1 = 1.f / lr1;
#pragma unroll
    for (int nt = 0; nt < 8; ++nt) {
        size_t c = (size_t)n * HD + nt * 8 + 2 * t4;
        float lx, ly;
        uint32_t h0 = pack_hi(accO[nt][0] * i0, accO[nt][1] * i0, lx, ly);
        uint32_t l0 = pack_lo(lx, ly);
        uint32_t h1 = pack_hi(accO[nt][2] * i1, accO[nt][3] * i1, lx, ly);
        uint32_t l1 = pack_lo(lx, ly);
        *(uint32_t*)(Oh + (size_t)r0 * EMB + c)       = h0;
        *(uint32_t*)(Ol + (size_t)r0 * EMB + c)       = l0;
        *(uint32_t*)(Oh + (size_t)(r0 + 8) * EMB + c) = h1;
        *(uint32_t*)(Ol + (size_t)(r0 + 8) * EMB + c) = l1;
    }
}

extern "C" void kernel_launch(void* const* d_in, const int* in_sizes, int n_in,
                              void* d_out, int out_size)
{
    (void)in_sizes; (void)n_in; (void)out_size;
    const float* x  = (const float*)d_in[0];
    const float* Wq = (const float*)d_in[1];
    const float* bq = (const float*)d_in[2];
    const float* Wk = (const float*)d_in[3];
    const float* bk = (const float*)d_in[4];
    const float* Wv = (const float*)d_in[5];
    const float* bv = (const float*)d_in[6];
    const float* Wo = (const float*)d_in[7];
    const float* bo = (const float*)d_in[8];
    const float* kc = (const float*)d_in[9];
    const float* vc = (const float*)d_in[10];
    const int*  pos = (const int*)d_in[11];
    float* out = (float*)d_out;

    float *Q, *K, *V;
    cudaGetSymbolAddress((void**)&Q, g_Q);
    cudaGetSymbolAddress((void**)&K, g_K);
    cudaGetSymbolAddress((void**)&V, g_V);
    __nv_bfloat16 *Qh, *Ql, *Oh, *Ol, *KH, *KL, *VH, *VL, *Wh, *Wl, *xh, *xl;
    cudaGetSymbolAddress((void**)&Qh, g_Qh);
    cudaGetSymbolAddress((void**)&Ql, g_Ql);
    cudaGetSymbolAddress((void**)&Oh, g_Oh);
    cudaGetSymbolAddress((void**)&Ol, g_Ol);
    cudaGetSymbolAddress((void**)&KH, g_KH);
    cudaGetSymbolAddress((void**)&KL, g_KL);
    cudaGetSymbolAddress((void**)&VH, g_VH);
    cudaGetSymbolAddress((void**)&VL, g_VL);
    cudaGetSymbolAddress((void**)&Wh, g_Wh);
    cudaGetSymbolAddress((void**)&Wl, g_Wl);
    cudaGetSymbolAddress((void**)&xh, g_xh);
    cudaGetSymbolAddress((void**)&xl, g_xl);

    cudaFuncSetAttribute(gemm_bf,
        cudaFuncAttributeMaxDynamicSharedMemorySize, 3 * GSTG);
    cudaFuncSetAttribute(attn_mma,
        cudaFuncAttributeMaxDynamicSharedMemorySize, 3 * ASTG);

    split_all<<<dim3(S_LEN * EMB / 4 / 256, 5), 256>>>(
        Wq, Wk, Wv, Wo, x, Wh, Wl, xh, xl);

    gemm_bf<<<dim3(EMB / 128, S_LEN / 128, 3), 256, 3 * GSTG>>>(
        xh, xl, Wh, Wl, 0, bq, bk, bv, Q, K, V);

    rope_prep<<<(S_LEN * NH * (HD / 2) + 255) / 256, 256>>>(Q, K, pos, Qh, Ql);

    prep_kv<<<(KVROWS * EMB / 4 + 255) / 256, 256>>>(
        K, V, kc, vc, KH, KL, VH, VL,
        out + (size_t)S_LEN * EMB,
        out + (size_t)S_LEN * EMB + (size_t)CLM1 * EMB);

    attn_mma<<<dim3(S_LEN / 128, NH), 256, 3 * ASTG>>>(
        Qh, Ql, KH, KL, VH, VL, Oh, Ol);

    gemm_bf<<<dim3(EMB / 128, S_LEN / 128, 1), 256, 3 * GSTG>>>(
        Oh, Ol, Wh, Wl, 3, bo, bo, bo, out, out, out);
}